// round 7
// baseline (speedup 1.0000x reference)
#include <cuda_runtime.h>

#define Nn   2048      // B*S
#define Bv   16
#define Sv   128
#define Hv   256
#define DINv 256
#define DEv  192
#define DRv  64
#define Ev   2032      // B*(S-1)
#define Lv   12
#define NCTA 128       // 16 trees x 8 column groups
#define NTHR 512
#define SMEM_BYTES 196608   // 48K floats: 32K weights + 16K scratch

// packed fp32x2 FMA (sm_103a FFMA2)
#define FFMA2(acc, a, b) asm("fma.rn.f32x2 %0, %1, %2, %0;" : "+l"(acc) : "l"(a), "l"(b))

__device__ __forceinline__ float pairsum(unsigned long long v) {
    float lo, hi;
    asm("mov.b64 {%0, %1}, %2;" : "=f"(lo), "=f"(hi) : "l"(v));
    return lo + hi;
}

// ---------------- device scratch (no allocations allowed) ----------------
__device__ float g_proj[4][Nn * Hv];   // i(+bi), f(+bf), o, u   (column-local)
__device__ float g_h[Nn * Hv];
__device__ float g_c[Nn * Hv];
__device__ float g_pooled[Bv * Hv];
__device__ int   g_coff[Nn + 1];
__device__ int   g_children[Ev];
__device__ int   g_tl_off[512];        // [16][32] per-tree level offsets
__device__ int   g_tl_nodes[Nn];       // per-tree level-bucketed node ids
__device__ int   g_tmax[Bv];
__device__ unsigned g_done[Nn];        // 8 = all column-CTAs wrote h/c of node
__device__ unsigned g_pdone[Bv * 32];  // pooling done count per tree

// fence-free release/acquire primitives (no CCTL.IVALL -> L1 stays warm)
__device__ __forceinline__ unsigned ld_acq(unsigned* p) {
    unsigned v;
    asm volatile("ld.acquire.gpu.global.u32 %0, [%1];" : "=r"(v) : "l"(p) : "memory");
    return v;
}
__device__ __forceinline__ void red_add_rel(unsigned* p, unsigned v) {
    asm volatile("red.release.gpu.global.add.u32 [%0], %1;" :: "l"(p), "r"(v) : "memory");
}

__device__ __forceinline__ float sigf(float x) {
    return 1.0f / (1.0f + __expf(-x));
}

// ---------------- setup: CSR + per-tree level buckets + flag reset --------
__global__ void setup_kernel(const int* __restrict__ child_idx,
                             const int* __restrict__ parent_idx,
                             const int* __restrict__ node_height) {
    __shared__ int cnt[Nn];
    __shared__ int psm[Ev];
    __shared__ int hsm[Nn];
    __shared__ int part[256];
    __shared__ int lvl[512];
    __shared__ int lfill[512];
    __shared__ int loff[512];
    const int tid = threadIdx.x;               // 1024 threads
    for (int i = tid; i < Nn; i += 1024) {
        cnt[i] = 0; hsm[i] = node_height[i];
        g_done[i] = 0u;                        // reset dataflow flags each launch
    }
    for (int i = tid; i < Ev; i += 1024) psm[i] = parent_idx[i];
    for (int i = tid; i < 512; i += 1024) { lvl[i] = 0; lfill[i] = 0; }
    if (tid < Bv) g_pdone[tid * 32] = 0u;
    __syncthreads();
    for (int e = tid; e < Ev; e += 1024) atomicAdd(&cnt[psm[e]], 1);
    for (int n = tid; n < Nn; n += 1024) atomicAdd(&lvl[(n >> 7) * 32 + hsm[n]], 1);
    __syncthreads();
    if (tid < 256) { int s = 0; for (int i = 0; i < 8; i++) s += cnt[tid * 8 + i]; part[tid] = s; }
    __syncthreads();
    if (tid == 0) {
        int run = 0;
        for (int i = 0; i < 256; i++) { int v = part[i]; part[i] = run; run += v; }
    }
    if (tid < 16) {                            // per-tree level prefix + maxlev
        int run = 0, mx = 1;
        for (int l = 0; l < 32; l++) {
            loff[tid * 32 + l] = tid * 128 + run;
            if (lvl[tid * 32 + l] > 0) mx = l;
            run += lvl[tid * 32 + l];
        }
        g_tmax[tid] = mx;
    }
    __syncthreads();
    for (int i = tid; i < 512; i += 1024) g_tl_off[i] = loff[i];
    if (tid < 256) {
        int run = part[tid];
        for (int i = 0; i < 8; i++) { int idx = tid * 8 + i; g_coff[idx] = run; run += cnt[idx]; }
        if (tid == 255) g_coff[Nn] = run;
    }
    __syncthreads();
    // deterministic CSR scatter: rank = #earlier same-parent edges (same batch)
    for (int e = tid; e < Ev; e += 1024) {
        int p = psm[e];
        int bstart = (e / (Sv - 1)) * (Sv - 1);
        int rank = 0;
        for (int e2 = bstart; e2 < e; e2++) rank += (psm[e2] == p);
        g_children[g_coff[p] + rank] = child_idx[e];
    }
    // per-tree level bucket fill (intra-level order numerically irrelevant)
    for (int n = tid; n < Nn; n += 1024) {
        int key = (n >> 7) * 32 + hsm[n];
        int r = atomicAdd(&lfill[key], 1);
        g_tl_nodes[loff[key] + r] = n;
    }
}

// helper select/accumulate macros (avoid dynamic register indexing)
#define FXSEL(MM) ((MM) == 0 ? fx0 : (MM) == 1 ? fx1 : (MM) == 2 ? fx2 : fx3)
#define ADD4(A, V) do { A.x += V.x; A.y += V.y; A.z += V.z; A.w += V.w; } while (0)
#define ACCS(MM, V0, V1) do { \
    if ((MM) == 0)      { ADD4(sA0, V0); ADD4(sB0, V1); } \
    else if ((MM) == 1) { ADD4(sA1, V0); ADD4(sB1, V1); } \
    else if ((MM) == 2) { ADD4(sA2, V0); ADD4(sB2, V1); } \
    else                { ADD4(sA3, V0); ADD4(sB3, V1); } } while (0)
#define FCADD(MM, V) do { \
    if ((MM) == 0) fc0 += (V); else if ((MM) == 1) fc1 += (V); \
    else if ((MM) == 2) fc2 += (V); else fc3 += (V); } while (0)
#define PUSH(CH, MM) do { \
    if (bc == 0)      { cc0 = (CH); cm0 = (MM); } \
    else if (bc == 1) { cc1 = (CH); cm1 = (MM); } \
    else if (bc == 2) { cc2 = (CH); cm2 = (MM); } \
    else              { cc3 = (CH); cm3 = (MM); } \
    bc++; if (bc == 4) { flush(4); bc = 0; } } while (0)

// ---------------- persistent kernel: barrier-free dataflow ----------------
__global__ void __launch_bounds__(NTHR, 1)
main_kernel(const int* __restrict__ xs, const int* __restrict__ rels,
            const float* __restrict__ emb_W, const float* __restrict__ rel_W,
            const float* __restrict__ W_ix, const float* __restrict__ b_ix,
            const float* __restrict__ W_ih, const float* __restrict__ b_ih,
            const float* __restrict__ W_fx, const float* __restrict__ b_fx,
            const float* __restrict__ W_fh, const float* __restrict__ b_fh,
            const float* __restrict__ W_ox, const float* __restrict__ W_oh,
            const float* __restrict__ W_ux, const float* __restrict__ W_uh,
            const float* __restrict__ W_out, const float* __restrict__ b_out,
            float* __restrict__ out) {
    extern __shared__ float sm[];
    float* Wi4 = sm;                  // [(k>>2)*128 + col*4 + (k&3)] layouts
    float* Wo4 = sm + 8192;
    float* Wu4 = sm + 16384;
    float* Wf4 = sm + 24576;
    float* scratch = sm + 32768;      // 16 warps x 1024 floats

    const int tid  = threadIdx.x;
    const int lane = tid & 31;
    const int warp = tid >> 5;
    const int blk  = blockIdx.x;
    const int b    = blk >> 3;        // tree id
    const int g    = blk & 7;         // column group
    const int J    = g * 32 + lane;

    // ---- load INPUT weight slices (cols J-block) -------------------------
    {
        const int jb2 = g * 32;
        for (int it = 0; it < 16; it++) {
            int k = it * 16 + (tid >> 5);
            int col = tid & 31;
            int didx = (k >> 2) * 128 + col * 4 + (k & 3);
            int sidx = k * Hv + jb2 + col;
            Wi4[didx] = W_ix[sidx];
            Wo4[didx] = W_ox[sidx];
            Wu4[didx] = W_ux[sidx];
            Wf4[didx] = W_fx[sidx];
        }
    }
    const float bi = b_ix[J] + b_ih[J];
    const float bf = b_fx[J] + b_fh[J];
    __syncthreads();

    // ---- P1: all 4 projections, columns J, this tree's 128 nodes ---------
    {
        float* xw = scratch + warp * 1024;
        for (int t = 0; t < 8; t++) {
            int n = b * Sv + warp + t * 16;
            __syncwarp();
            const float4* er = (const float4*)(emb_W + (size_t)xs[n] * DEv);
            const float4* rr = (const float4*)(rel_W + (size_t)rels[n] * DRv);
            float4 a = er[lane];
            float4 bb = (lane < 16) ? er[lane + 32] : rr[lane - 16];
            ((float4*)xw)[lane] = a; ((float4*)xw)[lane + 32] = bb;
            __syncwarp();
            unsigned long long aiX = 0, aiY = 0, aoX = 0, aoY = 0;
            unsigned long long auX = 0, auY = 0, afX = 0, afY = 0;
            #pragma unroll 4
            for (int k4 = 0; k4 < 64; k4++) {
                ulonglong2 xv = *(const ulonglong2*)&xw[k4 * 4];
                ulonglong2 wi = *(const ulonglong2*)&Wi4[k4 * 128 + lane * 4];
                ulonglong2 wo = *(const ulonglong2*)&Wo4[k4 * 128 + lane * 4];
                ulonglong2 wu = *(const ulonglong2*)&Wu4[k4 * 128 + lane * 4];
                ulonglong2 wf = *(const ulonglong2*)&Wf4[k4 * 128 + lane * 4];
                FFMA2(aiX, xv.x, wi.x); FFMA2(aiY, xv.y, wi.y);
                FFMA2(aoX, xv.x, wo.x); FFMA2(aoY, xv.y, wo.y);
                FFMA2(auX, xv.x, wu.x); FFMA2(auY, xv.y, wu.y);
                FFMA2(afX, xv.x, wf.x); FFMA2(afY, xv.y, wf.y);
            }
            size_t nx = (size_t)n * Hv + J;
            g_proj[0][nx] = pairsum(aiX) + pairsum(aiY) + bi;
            g_proj[1][nx] = pairsum(afX) + pairsum(afY) + bf;
            g_proj[2][nx] = pairsum(aoX) + pairsum(aoY);
            g_proj[3][nx] = pairsum(auX) + pairsum(auY);
        }
    }
    __syncthreads();

    // ---- reload RECURRENT weight slices (same regions) -------------------
    {
        const int jb2 = g * 32;
        for (int it = 0; it < 16; it++) {
            int k = it * 16 + (tid >> 5);
            int col = tid & 31;
            int didx = (k >> 2) * 128 + col * 4 + (k & 3);
            int sidx = k * Hv + jb2 + col;
            Wi4[didx] = W_ih[sidx];
            Wo4[didx] = W_oh[sidx];
            Wu4[didx] = W_uh[sidx];
            Wf4[didx] = W_fh[sidx];
        }
    }
    __syncthreads();

    // ---- leaves (level 0): elementwise; release done as we go ------------
    {
        int lb = g_tl_off[b * 32];
        int le = g_tl_off[b * 32 + 1];
        for (int idx = lb + warp; idx < le; idx += 16) {
            int n = g_tl_nodes[idx];
            size_t nx = (size_t)n * Hv + J;
            float iv = sigf(g_proj[0][nx]);
            float ov = sigf(g_proj[2][nx]);
            float uv = __tanhf(g_proj[3][nx]);
            float cv = iv * uv;
            g_c[nx] = cv;
            g_h[nx] = ov * __tanhf(cv);
            __syncwarp();
            if (lane == 0) red_add_rel(&g_done[n], 1u);
        }
    }

    // ---- non-leaf levels: barrier-free; chunks within a level only -------
    {
        float* hb = scratch + warp * 1024;
        const int tmax = g_tmax[b];
        for (int lev = 1; lev <= tmax; lev++) {
            int base = g_tl_off[b * 32 + lev];
            int cntl = g_tl_off[b * 32 + lev + 1] - base;
            int nch  = (cntl + 3) >> 2;
            for (int chunk = warp; chunk < nch; chunk += 16) {
                int i0 = base + chunk * 4;
                int mc = cntl - chunk * 4; if (mc > 4) mc = 4;
                int n0 = g_tl_nodes[i0];
                int n1 = (mc > 1) ? g_tl_nodes[i0 + 1] : -1;
                int n2 = (mc > 2) ? g_tl_nodes[i0 + 2] : -1;
                int n3 = (mc > 3) ? g_tl_nodes[i0 + 3] : -1;
                float fx0 = g_proj[1][(size_t)n0 * Hv + J];
                float fx1 = (n1 >= 0) ? g_proj[1][(size_t)n1 * Hv + J] : 0.0f;
                float fx2 = (n2 >= 0) ? g_proj[1][(size_t)n2 * Hv + J] : 0.0f;
                float fx3 = (n3 >= 0) ? g_proj[1][(size_t)n3 * Hv + J] : 0.0f;
                float4 z4 = make_float4(0, 0, 0, 0);
                float4 sA0 = z4, sB0 = z4, sA1 = z4, sB1 = z4;
                float4 sA2 = z4, sB2 = z4, sA3 = z4, sB3 = z4;
                float fc0 = 0, fc1 = 0, fc2 = 0, fc3 = 0;
                int bc = 0, cc0 = 0, cc1 = 0, cc2 = 0, cc3 = 0;
                int cm0 = 0, cm1 = 0, cm2 = 0, cm3 = 0;

                auto flush = [&](int kk) {
                    // concurrent per-lane polls of all kk children
                    int myc = (lane == 0) ? cc0 : (lane == 1) ? cc1
                             : (lane == 2) ? cc2 : cc3;
                    for (;;) {
                        unsigned d = (lane < kk) ? ld_acq(&g_done[myc]) : 8u;
                        if (__all_sync(0xFFFFFFFFu, d >= 8u)) break;
                    }
                    const float* h0p = g_h + (size_t)cc0 * Hv;
                    const float* h1p = g_h + (size_t)cc1 * Hv;
                    const float* h2p = g_h + (size_t)cc2 * Hv;
                    const float* h3p = g_h + (size_t)cc3 * Hv;
                    {   // h_sum accumulation (also warms L1 rows)
                        float4 v0 = *(const float4*)(h0p + lane * 4);
                        float4 v1 = *(const float4*)(h0p + 128 + lane * 4);
                        ACCS(cm0, v0, v1);
                        if (kk > 1) {
                            v0 = *(const float4*)(h1p + lane * 4);
                            v1 = *(const float4*)(h1p + 128 + lane * 4);
                            ACCS(cm1, v0, v1);
                        }
                        if (kk > 2) {
                            v0 = *(const float4*)(h2p + lane * 4);
                            v1 = *(const float4*)(h2p + 128 + lane * 4);
                            ACCS(cm2, v0, v1);
                        }
                        if (kk > 3) {
                            v0 = *(const float4*)(h3p + lane * 4);
                            v1 = *(const float4*)(h3p + 128 + lane * 4);
                            ACCS(cm3, v0, v1);
                        }
                    }
                    // batched fh = W_fh . h_ch (x via broadcast LDG, L1-warm)
                    unsigned long long a0x = 0, a0y = 0, a1x = 0, a1y = 0;
                    unsigned long long a2x = 0, a2y = 0, a3x = 0, a3y = 0;
                    #pragma unroll 4
                    for (int k4 = 0; k4 < 64; k4++) {
                        ulonglong2 wf = *(const ulonglong2*)&Wf4[k4 * 128 + lane * 4];
                        ulonglong2 x0 = *(const ulonglong2*)(h0p + k4 * 4);
                        FFMA2(a0x, x0.x, wf.x); FFMA2(a0y, x0.y, wf.y);
                        if (kk > 1) {
                            ulonglong2 x1 = *(const ulonglong2*)(h1p + k4 * 4);
                            FFMA2(a1x, x1.x, wf.x); FFMA2(a1y, x1.y, wf.y);
                        }
                        if (kk > 2) {
                            ulonglong2 x2 = *(const ulonglong2*)(h2p + k4 * 4);
                            FFMA2(a2x, x2.x, wf.x); FFMA2(a2y, x2.y, wf.y);
                        }
                        if (kk > 3) {
                            ulonglong2 x3 = *(const ulonglong2*)(h3p + k4 * 4);
                            FFMA2(a3x, x3.x, wf.x); FFMA2(a3y, x3.y, wf.y);
                        }
                    }
                    {
                        float f = sigf(pairsum(a0x) + pairsum(a0y) + FXSEL(cm0));
                        FCADD(cm0, f * g_c[(size_t)cc0 * Hv + J]);
                    }
                    if (kk > 1) {
                        float f = sigf(pairsum(a1x) + pairsum(a1y) + FXSEL(cm1));
                        FCADD(cm1, f * g_c[(size_t)cc1 * Hv + J]);
                    }
                    if (kk > 2) {
                        float f = sigf(pairsum(a2x) + pairsum(a2y) + FXSEL(cm2));
                        FCADD(cm2, f * g_c[(size_t)cc2 * Hv + J]);
                    }
                    if (kk > 3) {
                        float f = sigf(pairsum(a3x) + pairsum(a3y) + FXSEL(cm3));
                        FCADD(cm3, f * g_c[(size_t)cc3 * Hv + J]);
                    }
                };

                // stream this chunk's edges through the 4-slot batch buffer
                {
                    int csx = g_coff[n0], cex = g_coff[n0 + 1];
                    for (int ci = csx; ci < cex; ci++) PUSH(g_children[ci], 0);
                }
                if (n1 >= 0) {
                    int csx = g_coff[n1], cex = g_coff[n1 + 1];
                    for (int ci = csx; ci < cex; ci++) PUSH(g_children[ci], 1);
                }
                if (n2 >= 0) {
                    int csx = g_coff[n2], cex = g_coff[n2 + 1];
                    for (int ci = csx; ci < cex; ci++) PUSH(g_children[ci], 2);
                }
                if (n3 >= 0) {
                    int csx = g_coff[n3], cex = g_coff[n3 + 1];
                    for (int ci = csx; ci < cex; ci++) PUSH(g_children[ci], 3);
                }
                if (bc > 0) { flush(bc); bc = 0; }

                // gate matvecs on h_sum (batched over the chunk's nodes)
                __syncwarp();
                ((float4*)(hb + 0))[lane]   = sA0; ((float4*)(hb + 128))[lane] = sB0;
                ((float4*)(hb + 256))[lane] = sA1; ((float4*)(hb + 384))[lane] = sB1;
                ((float4*)(hb + 512))[lane] = sA2; ((float4*)(hb + 640))[lane] = sB2;
                ((float4*)(hb + 768))[lane] = sA3; ((float4*)(hb + 896))[lane] = sB3;
                __syncwarp();
                unsigned long long ai0 = 0, ai1 = 0, ai2 = 0, ai3 = 0;
                unsigned long long ao0 = 0, ao1 = 0, ao2 = 0, ao3 = 0;
                #pragma unroll 2
                for (int k4 = 0; k4 < 64; k4++) {
                    ulonglong2 wi = *(const ulonglong2*)&Wi4[k4 * 128 + lane * 4];
                    ulonglong2 wo = *(const ulonglong2*)&Wo4[k4 * 128 + lane * 4];
                    ulonglong2 x0 = *(const ulonglong2*)&hb[k4 * 4];
                    ulonglong2 x1 = *(const ulonglong2*)&hb[256 + k4 * 4];
                    ulonglong2 x2 = *(const ulonglong2*)&hb[512 + k4 * 4];
                    ulonglong2 x3 = *(const ulonglong2*)&hb[768 + k4 * 4];
                    FFMA2(ai0, x0.x, wi.x); FFMA2(ai0, x0.y, wi.y);
                    FFMA2(ai1, x1.x, wi.x); FFMA2(ai1, x1.y, wi.y);
                    FFMA2(ai2, x2.x, wi.x); FFMA2(ai2, x2.y, wi.y);
                    FFMA2(ai3, x3.x, wi.x); FFMA2(ai3, x3.y, wi.y);
                    FFMA2(ao0, x0.x, wo.x); FFMA2(ao0, x0.y, wo.y);
                    FFMA2(ao1, x1.x, wo.x); FFMA2(ao1, x1.y, wo.y);
                    FFMA2(ao2, x2.x, wo.x); FFMA2(ao2, x2.y, wo.y);
                    FFMA2(ao3, x3.x, wo.x); FFMA2(ao3, x3.y, wo.y);
                }
                float pi0 = pairsum(ai0), pi1 = pairsum(ai1);
                float pi2 = pairsum(ai2), pi3 = pairsum(ai3);
                float po0 = pairsum(ao0), po1 = pairsum(ao1);
                float po2 = pairsum(ao2), po3 = pairsum(ao3);
                unsigned long long au0 = 0, au1 = 0, au2 = 0, au3 = 0;
                #pragma unroll 2
                for (int k4 = 0; k4 < 64; k4++) {
                    ulonglong2 wu = *(const ulonglong2*)&Wu4[k4 * 128 + lane * 4];
                    ulonglong2 x0 = *(const ulonglong2*)&hb[k4 * 4];
                    ulonglong2 x1 = *(const ulonglong2*)&hb[256 + k4 * 4];
                    ulonglong2 x2 = *(const ulonglong2*)&hb[512 + k4 * 4];
                    ulonglong2 x3 = *(const ulonglong2*)&hb[768 + k4 * 4];
                    FFMA2(au0, x0.x, wu.x); FFMA2(au0, x0.y, wu.y);
                    FFMA2(au1, x1.x, wu.x); FFMA2(au1, x1.y, wu.y);
                    FFMA2(au2, x2.x, wu.x); FFMA2(au2, x2.y, wu.y);
                    FFMA2(au3, x3.x, wu.x); FFMA2(au3, x3.y, wu.y);
                }
                {
                    size_t nx = (size_t)n0 * Hv + J;
                    float iv = sigf(g_proj[0][nx] + pi0);
                    float ov = sigf(g_proj[2][nx] + po0);
                    float uv = __tanhf(g_proj[3][nx] + pairsum(au0));
                    float cn = iv * uv + fc0;
                    g_c[nx] = cn; g_h[nx] = ov * __tanhf(cn);
                }
                if (n1 >= 0) {
                    size_t nx = (size_t)n1 * Hv + J;
                    float iv = sigf(g_proj[0][nx] + pi1);
                    float ov = sigf(g_proj[2][nx] + po1);
                    float uv = __tanhf(g_proj[3][nx] + pairsum(au1));
                    float cn = iv * uv + fc1;
                    g_c[nx] = cn; g_h[nx] = ov * __tanhf(cn);
                }
                if (n2 >= 0) {
                    size_t nx = (size_t)n2 * Hv + J;
                    float iv = sigf(g_proj[0][nx] + pi2);
                    float ov = sigf(g_proj[2][nx] + po2);
                    float uv = __tanhf(g_proj[3][nx] + pairsum(au2));
                    float cn = iv * uv + fc2;
                    g_c[nx] = cn; g_h[nx] = ov * __tanhf(cn);
                }
                if (n3 >= 0) {
                    size_t nx = (size_t)n3 * Hv + J;
                    float iv = sigf(g_proj[0][nx] + pi3);
                    float ov = sigf(g_proj[2][nx] + po3);
                    float uv = __tanhf(g_proj[3][nx] + pairsum(au3));
                    float cn = iv * uv + fc3;
                    g_c[nx] = cn; g_h[nx] = ov * __tanhf(cn);
                }
                __syncwarp();
                if (lane < mc) {
                    int nn = g_tl_nodes[i0 + lane];
                    red_add_rel(&g_done[nn], 1u);
                }
            }
        }
    }

    // ---- pooling (column-local) + head -----------------------------------
    __syncthreads();                 // all my columns of all nodes done
    {
        float m = -1e30f;
        for (int s2 = warp; s2 < Sv; s2 += 16)
            m = fmaxf(m, g_h[(size_t)(b * Sv + s2) * Hv + J]);
        scratch[warp * 32 + lane] = m;
        __syncthreads();
        if (tid < 32) {
            float mm = scratch[tid];
            #pragma unroll
            for (int r = 1; r < 16; r++) mm = fmaxf(mm, scratch[r * 32 + tid]);
            g_pooled[b * Hv + g * 32 + tid] = mm;
        }
        __syncthreads();
        if (tid == 0) red_add_rel(&g_pdone[b * 32], 1u);
    }
    if (g == 0) {
        if (tid == 0) { while (ld_acq(&g_pdone[b * 32]) < 8u) { } }
        __syncthreads();
        if (warp < Lv) {
            float acc = 0.0f;
            for (int k = lane; k < Hv; k += 32)
                acc += g_pooled[b * Hv + k] * W_out[k * Lv + warp];
            #pragma unroll
            for (int off = 16; off; off >>= 1)
                acc += __shfl_down_sync(0xFFFFFFFFu, acc, off);
            if (lane == 0) out[b * Lv + warp] = acc + b_out[warp];
        }
    }
}

// ---------------- launch --------------------------------------------------
extern "C" void kernel_launch(void* const* d_in, const int* in_sizes, int n_in,
                              void* d_out, int out_size) {
    const int s = (n_in >= 22) ? 1 : 0;   // robust to n_levels scalar presence
    const int* xs          = (const int*)d_in[0];
    const int* rels        = (const int*)d_in[1];
    const int* child_idx   = (const int*)d_in[2];
    const int* parent_idx  = (const int*)d_in[3];
    const int* node_height = (const int*)d_in[4];
    const float* emb_W = (const float*)d_in[5 + s];
    const float* rel_W = (const float*)d_in[6 + s];
    const float* W_ix  = (const float*)d_in[7 + s];
    const float* b_ix  = (const float*)d_in[8 + s];
    const float* W_ih  = (const float*)d_in[9 + s];
    const float* b_ih  = (const float*)d_in[10 + s];
    const float* W_fx  = (const float*)d_in[11 + s];
    const float* b_fx  = (const float*)d_in[12 + s];
    const float* W_fh  = (const float*)d_in[13 + s];
    const float* b_fh  = (const float*)d_in[14 + s];
    const float* W_ox  = (const float*)d_in[15 + s];
    const float* W_oh  = (const float*)d_in[16 + s];
    const float* W_ux  = (const float*)d_in[17 + s];
    const float* W_uh  = (const float*)d_in[18 + s];
    const float* W_out = (const float*)d_in[19 + s];
    const float* b_out = (const float*)d_in[20 + s];
    float* out = (float*)d_out;

    cudaFuncSetAttribute(main_kernel, cudaFuncAttributeMaxDynamicSharedMemorySize, SMEM_BYTES);

    setup_kernel<<<1, 1024>>>(child_idx, parent_idx, node_height);
    main_kernel<<<NCTA, NTHR, SMEM_BYTES>>>(xs, rels, emb_W, rel_W,
                                            W_ix, b_ix, W_ih, b_ih,
                                            W_fx, b_fx, W_fh, b_fh,
                                            W_ox, W_oh, W_ux, W_uh,
                                            W_out, b_out, out);
}

// round 8
// speedup vs baseline: 1.1453x; 1.1453x over previous
#include <cuda_runtime.h>

#define Nn   2048      // B*S
#define Bv   16
#define Sv   128
#define Hv   256
#define DINv 256
#define DEv  192
#define DRv  64
#define Ev   2032      // B*(S-1)
#define Lv   12
#define NCTA 128       // 16 trees x 8 column groups
#define NTHR 512
#define NLEVF 24
#define SMEM_BYTES 196608   // 48K floats: 32K weights + 16K scratch

// packed fp32x2 FMA (sm_103a FFMA2)
#define FFMA2(acc, a, b) asm("fma.rn.f32x2 %0, %1, %2, %0;" : "+l"(acc) : "l"(a), "l"(b))

__device__ __forceinline__ float pairsum(unsigned long long v) {
    float lo, hi;
    asm("mov.b64 {%0, %1}, %2;" : "=f"(lo), "=f"(hi) : "l"(v));
    return lo + hi;
}

// ---------------- device scratch (no allocations allowed) ----------------
__device__ float g_proj[4][Nn * Hv];   // i(+bi+bih), f(+bf+bfh), o, u  (column-local)
__device__ float g_h[Nn * Hv];
__device__ float g_c[Nn * Hv];         // column-local
__device__ float g_pfh[(size_t)Nn * 2048];  // [n][8 ctas][256 cols] partial W_fh.h
__device__ float g_pooled[Bv * Hv];
__device__ int   g_coff[Nn + 1];
__device__ int   g_children[Ev];
__device__ int   g_tl_off[512];        // [16][32] per-tree level offsets
__device__ int   g_tl_nodes[Nn];
__device__ int   g_tmax[Bv];
__device__ unsigned g_lflag[Bv * NLEVF * 8];  // per-tree per-level per-CTA flag
__device__ unsigned g_pdone[Bv * 32];

// fence-free release/acquire primitives (no CCTL.IVALL -> L1 stays warm)
__device__ __forceinline__ unsigned ld_acq(unsigned* p) {
    unsigned v;
    asm volatile("ld.acquire.gpu.global.u32 %0, [%1];" : "=r"(v) : "l"(p) : "memory");
    return v;
}
__device__ __forceinline__ void st_rel(unsigned* p, unsigned v) {
    asm volatile("st.release.gpu.global.u32 [%0], %1;" :: "l"(p), "r"(v) : "memory");
}
__device__ __forceinline__ void red_add_rel(unsigned* p, unsigned v) {
    asm volatile("red.release.gpu.global.add.u32 [%0], %1;" :: "l"(p), "r"(v) : "memory");
}

__device__ __forceinline__ float sigf(float x) {
    return 1.0f / (1.0f + __expf(-x));
}

// ---------------- setup: CSR + per-tree level buckets + flag reset --------
__global__ void setup_kernel(const int* __restrict__ child_idx,
                             const int* __restrict__ parent_idx,
                             const int* __restrict__ node_height) {
    __shared__ int cnt[Nn];
    __shared__ int psm[Ev];
    __shared__ int hsm[Nn];
    __shared__ int part[256];
    __shared__ int lvl[512];
    __shared__ int lfill[512];
    __shared__ int loff[512];
    const int tid = threadIdx.x;               // 1024 threads
    for (int i = tid; i < Nn; i += 1024) { cnt[i] = 0; hsm[i] = node_height[i]; }
    for (int i = tid; i < Ev; i += 1024) psm[i] = parent_idx[i];
    for (int i = tid; i < 512; i += 1024) { lvl[i] = 0; lfill[i] = 0; }
    for (int i = tid; i < Bv * NLEVF * 8; i += 1024) g_lflag[i] = 0u;
    if (tid < Bv) g_pdone[tid * 32] = 0u;
    __syncthreads();
    for (int e = tid; e < Ev; e += 1024) atomicAdd(&cnt[psm[e]], 1);
    for (int n = tid; n < Nn; n += 1024) atomicAdd(&lvl[(n >> 7) * 32 + hsm[n]], 1);
    __syncthreads();
    if (tid < 256) { int s = 0; for (int i = 0; i < 8; i++) s += cnt[tid * 8 + i]; part[tid] = s; }
    __syncthreads();
    if (tid == 0) {
        int run = 0;
        for (int i = 0; i < 256; i++) { int v = part[i]; part[i] = run; run += v; }
    }
    if (tid < 16) {                            // per-tree level prefix + maxlev
        int run = 0, mx = 1;
        for (int l = 0; l < 32; l++) {
            loff[tid * 32 + l] = tid * 128 + run;
            if (lvl[tid * 32 + l] > 0) mx = l;
            run += lvl[tid * 32 + l];
        }
        g_tmax[tid] = mx;
    }
    __syncthreads();
    for (int i = tid; i < 512; i += 1024) g_tl_off[i] = loff[i];
    if (tid < 256) {
        int run = part[tid];
        for (int i = 0; i < 8; i++) { int idx = tid * 8 + i; g_coff[idx] = run; run += cnt[idx]; }
        if (tid == 255) g_coff[Nn] = run;
    }
    __syncthreads();
    // deterministic CSR scatter: rank = #earlier same-parent edges (same batch)
    for (int e = tid; e < Ev; e += 1024) {
        int p = psm[e];
        int bstart = (e / (Sv - 1)) * (Sv - 1);
        int rank = 0;
        for (int e2 = bstart; e2 < e; e2++) rank += (psm[e2] == p);
        g_children[g_coff[p] + rank] = child_idx[e];
    }
    // per-tree level bucket fill (intra-level order numerically irrelevant)
    for (int n = tid; n < Nn; n += 1024) {
        int key = (n >> 7) * 32 + hsm[n];
        int r = atomicAdd(&lfill[key], 1);
        g_tl_nodes[loff[key] + r] = n;
    }
}

// --- partial fh for a chunk of <=4 nodes: this CTA's 32 h-rows x 256 cols --
// WfR layout: WfR[kp*512 + lane*16 + jj*2 + kb] = W_fh[(g*32+2kp+kb)*256 + jj*32+lane]
__device__ __forceinline__ void pfh_chunk(const float* WfR, float* hb, int lane, int g,
                                          int n0, int n1, int n2, int n3,
                                          float h0, float h1, float h2, float h3) {
    __syncwarp();
    hb[lane] = h0; hb[32 + lane] = h1; hb[64 + lane] = h2; hb[96 + lane] = h3;
    __syncwarp();
    #pragma unroll
    for (int jq = 0; jq < 4; jq++) {
        unsigned long long A00 = 0, A01 = 0, A10 = 0, A11 = 0;
        unsigned long long A20 = 0, A21 = 0, A30 = 0, A31 = 0;
        #pragma unroll 4
        for (int kp = 0; kp < 16; kp++) {
            ulonglong2 w = *(const ulonglong2*)&WfR[kp * 512 + lane * 16 + jq * 4];
            unsigned long long hp0 = *(const unsigned long long*)&hb[2 * kp];
            unsigned long long hp1 = *(const unsigned long long*)&hb[32 + 2 * kp];
            unsigned long long hp2 = *(const unsigned long long*)&hb[64 + 2 * kp];
            unsigned long long hp3 = *(const unsigned long long*)&hb[96 + 2 * kp];
            FFMA2(A00, hp0, w.x); FFMA2(A01, hp0, w.y);
            FFMA2(A10, hp1, w.x); FFMA2(A11, hp1, w.y);
            FFMA2(A20, hp2, w.x); FFMA2(A21, hp2, w.y);
            FFMA2(A30, hp3, w.x); FFMA2(A31, hp3, w.y);
        }
        int Jp = (2 * jq) * 32 + lane;           // jj = 2*jq (+1 for second col)
        if (n0 >= 0) { size_t bb = (size_t)n0 * 2048 + g * 256 + Jp;
            g_pfh[bb] = pairsum(A00); g_pfh[bb + 32] = pairsum(A01); }
        if (n1 >= 0) { size_t bb = (size_t)n1 * 2048 + g * 256 + Jp;
            g_pfh[bb] = pairsum(A10); g_pfh[bb + 32] = pairsum(A11); }
        if (n2 >= 0) { size_t bb = (size_t)n2 * 2048 + g * 256 + Jp;
            g_pfh[bb] = pairsum(A20); g_pfh[bb + 32] = pairsum(A21); }
        if (n3 >= 0) { size_t bb = (size_t)n3 * 2048 + g * 256 + Jp;
            g_pfh[bb] = pairsum(A30); g_pfh[bb + 32] = pairsum(A31); }
    }
}

// ---------------- persistent kernel: per-tree, 1 phase + 1 flag/level -----
__global__ void __launch_bounds__(NTHR, 1)
main_kernel(const int* __restrict__ xs, const int* __restrict__ rels,
            const float* __restrict__ emb_W, const float* __restrict__ rel_W,
            const float* __restrict__ W_ix, const float* __restrict__ b_ix,
            const float* __restrict__ W_ih, const float* __restrict__ b_ih,
            const float* __restrict__ W_fx, const float* __restrict__ b_fx,
            const float* __restrict__ W_fh, const float* __restrict__ b_fh,
            const float* __restrict__ W_ox, const float* __restrict__ W_oh,
            const float* __restrict__ W_ux, const float* __restrict__ W_uh,
            const float* __restrict__ W_out, const float* __restrict__ b_out,
            float* __restrict__ out) {
    extern __shared__ float sm[];
    float* Wi4 = sm;                  // col-slice layout [(k>>2)*128 + col*4 + (k&3)]
    float* Wo4 = sm + 8192;
    float* Wu4 = sm + 16384;
    float* Wf  = sm + 24576;          // P1: W_fx col-slice; P3: WfR row-slice
    float* scratch = sm + 32768;      // 16 warps x 1024 floats

    const int tid  = threadIdx.x;
    const int lane = tid & 31;
    const int warp = tid >> 5;
    const int blk  = blockIdx.x;
    const int b    = blk >> 3;        // tree id
    const int g    = blk & 7;         // column group
    const int J    = g * 32 + lane;

    // ---- load INPUT weight col-slices ------------------------------------
    {
        const int jb2 = g * 32;
        for (int it = 0; it < 16; it++) {
            int k = it * 16 + (tid >> 5);
            int col = tid & 31;
            int didx = (k >> 2) * 128 + col * 4 + (k & 3);
            int sidx = k * Hv + jb2 + col;
            Wi4[didx] = W_ix[sidx];
            Wo4[didx] = W_ox[sidx];
            Wu4[didx] = W_ux[sidx];
            Wf[didx]  = W_fx[sidx];
        }
    }
    const float bi = b_ix[J] + b_ih[J];
    const float bf = b_fx[J] + b_fh[J];
    __syncthreads();

    // ---- P1: all 4 projections, columns J, this tree's 128 nodes ---------
    {
        float* xw = scratch + warp * 1024;
        for (int t = 0; t < 8; t++) {
            int n = b * Sv + warp + t * 16;
            __syncwarp();
            const float4* er = (const float4*)(emb_W + (size_t)xs[n] * DEv);
            const float4* rr = (const float4*)(rel_W + (size_t)rels[n] * DRv);
            float4 a = er[lane];
            float4 bb = (lane < 16) ? er[lane + 32] : rr[lane - 16];
            ((float4*)xw)[lane] = a; ((float4*)xw)[lane + 32] = bb;
            __syncwarp();
            unsigned long long aiX = 0, aiY = 0, aoX = 0, aoY = 0;
            unsigned long long auX = 0, auY = 0, afX = 0, afY = 0;
            #pragma unroll 4
            for (int k4 = 0; k4 < 64; k4++) {
                ulonglong2 xv = *(const ulonglong2*)&xw[k4 * 4];
                ulonglong2 wi = *(const ulonglong2*)&Wi4[k4 * 128 + lane * 4];
                ulonglong2 wo = *(const ulonglong2*)&Wo4[k4 * 128 + lane * 4];
                ulonglong2 wu = *(const ulonglong2*)&Wu4[k4 * 128 + lane * 4];
                ulonglong2 wf = *(const ulonglong2*)&Wf[k4 * 128 + lane * 4];
                FFMA2(aiX, xv.x, wi.x); FFMA2(aiY, xv.y, wi.y);
                FFMA2(aoX, xv.x, wo.x); FFMA2(aoY, xv.y, wo.y);
                FFMA2(auX, xv.x, wu.x); FFMA2(auY, xv.y, wu.y);
                FFMA2(afX, xv.x, wf.x); FFMA2(afY, xv.y, wf.y);
            }
            size_t nx = (size_t)n * Hv + J;
            g_proj[0][nx] = pairsum(aiX) + pairsum(aiY) + bi;
            g_proj[1][nx] = pairsum(afX) + pairsum(afY) + bf;
            g_proj[2][nx] = pairsum(aoX) + pairsum(aoY);
            g_proj[3][nx] = pairsum(auX) + pairsum(auY);
        }
    }
    __syncthreads();

    // ---- reload RECURRENT weights: col-slices + W_fh row-slice -----------
    {
        const int jb2 = g * 32;
        for (int it = 0; it < 16; it++) {
            int k = it * 16 + (tid >> 5);
            int col = tid & 31;
            int didx = (k >> 2) * 128 + col * 4 + (k & 3);
            int sidx = k * Hv + jb2 + col;
            Wi4[didx] = W_ih[sidx];
            Wo4[didx] = W_oh[sidx];
            Wu4[didx] = W_uh[sidx];
        }
        for (int idx = tid; idx < 8192; idx += NTHR) {
            int kp = idx >> 9, r = idx & 511;
            int lane_ = r >> 4, r2 = r & 15;
            int jj = r2 >> 1, kb = r2 & 1;
            Wf[idx] = W_fh[(g * 32 + kp * 2 + kb) * Hv + jj * 32 + lane_];
        }
    }
    __syncthreads();

    // ---- level 0 (leaves): elementwise + partial fh ----------------------
    {
        float* hb = scratch + warp * 1024;
        int base = g_tl_off[b * 32];
        int cntl = g_tl_off[b * 32 + 1] - base;
        int nch = (cntl + 3) >> 2;
        for (int chunk = warp; chunk < nch; chunk += 16) {
            int i0 = base + chunk * 4;
            int mc = cntl - chunk * 4; if (mc > 4) mc = 4;
            int nid[4]; float hv[4];
            #pragma unroll
            for (int m = 0; m < 4; m++) {
                if (m < mc) {
                    int n = g_tl_nodes[i0 + m];
                    nid[m] = n;
                    size_t nx = (size_t)n * Hv + J;
                    float iv = sigf(g_proj[0][nx]);
                    float ov = sigf(g_proj[2][nx]);
                    float uv = __tanhf(g_proj[3][nx]);
                    float cv = iv * uv;
                    g_c[nx] = cv;
                    float hh = ov * __tanhf(cv);
                    g_h[nx] = hh;
                    hv[m] = hh;
                } else { nid[m] = -1; hv[m] = 0.0f; }
            }
            pfh_chunk(Wf, hb, lane, g, nid[0], nid[1], nid[2], nid[3],
                      hv[0], hv[1], hv[2], hv[3]);
        }
    }
    __syncthreads();
    if (tid == 0) st_rel(&g_lflag[(b * NLEVF + 0) * 8 + g], 1u);

    // ---- bottom-up levels: one phase + one flag per level ----------------
    {
        float* hbw = scratch + warp * 1024;   // 4 nodes x 256 (h_sum staging)
        const int tmax = g_tmax[b];
        for (int lev = 1; lev <= tmax; lev++) {
            // one-hop wait: all 8 CTAs of my tree published level lev-1
            if (tid < 8) {
                unsigned* fp = &g_lflag[(b * NLEVF + lev - 1) * 8 + tid];
                while (ld_acq(fp) == 0u) { }
            }
            __syncthreads();

            int base = g_tl_off[b * 32 + lev];
            int cntl = g_tl_off[b * 32 + lev + 1] - base;
            int nch = (cntl + 3) >> 2;
            for (int chunk = warp; chunk < nch; chunk += 16) {
                int i0 = base + chunk * 4;
                int mc = cntl - chunk * 4; if (mc > 4) mc = 4;
                int nid[4]; float fcv[4];
                __syncwarp();
                #pragma unroll
                for (int m = 0; m < 4; m++) {
                    fcv[m] = 0.0f;
                    if (m < mc) {
                        int n = g_tl_nodes[i0 + m];
                        nid[m] = n;
                        float fxv = g_proj[1][(size_t)n * Hv + J];
                        int cs = g_coff[n], ce = g_coff[n + 1];
                        float4 s0 = make_float4(0, 0, 0, 0), s1 = make_float4(0, 0, 0, 0);
                        float fc = 0.0f;
                        for (int ci = cs; ci < ce; ci++) {
                            int ch = g_children[ci];
                            const float4* hsrc = (const float4*)(g_h + (size_t)ch * Hv);
                            float4 v0 = hsrc[lane], v1 = hsrc[lane + 32];
                            s0.x += v0.x; s0.y += v0.y; s0.z += v0.z; s0.w += v0.w;
                            s1.x += v1.x; s1.y += v1.y; s1.z += v1.z; s1.w += v1.w;
                            const float* pp = g_pfh + (size_t)ch * 2048 + J;
                            float ps = ((pp[0] + pp[256]) + (pp[512] + pp[768]))
                                     + ((pp[1024] + pp[1280]) + (pp[1536] + pp[1792]));
                            fc += sigf(ps + fxv) * g_c[(size_t)ch * Hv + J];
                        }
                        float4* dm = (float4*)(hbw + m * 256);
                        dm[lane] = s0; dm[lane + 32] = s1;
                        fcv[m] = fc;
                    } else nid[m] = -1;
                }
                __syncwarp();
                unsigned long long ai0 = 0, ai1 = 0, ai2 = 0, ai3 = 0;
                unsigned long long ao0 = 0, ao1 = 0, ao2 = 0, ao3 = 0;
                #pragma unroll 2
                for (int k4 = 0; k4 < 64; k4++) {
                    ulonglong2 wi = *(const ulonglong2*)&Wi4[k4 * 128 + lane * 4];
                    ulonglong2 wo = *(const ulonglong2*)&Wo4[k4 * 128 + lane * 4];
                    ulonglong2 x0 = *(const ulonglong2*)&hbw[k4 * 4];
                    ulonglong2 x1 = *(const ulonglong2*)&hbw[256 + k4 * 4];
                    ulonglong2 x2 = *(const ulonglong2*)&hbw[512 + k4 * 4];
                    ulonglong2 x3 = *(const ulonglong2*)&hbw[768 + k4 * 4];
                    FFMA2(ai0, x0.x, wi.x); FFMA2(ai0, x0.y, wi.y);
                    FFMA2(ai1, x1.x, wi.x); FFMA2(ai1, x1.y, wi.y);
                    FFMA2(ai2, x2.x, wi.x); FFMA2(ai2, x2.y, wi.y);
                    FFMA2(ai3, x3.x, wi.x); FFMA2(ai3, x3.y, wi.y);
                    FFMA2(ao0, x0.x, wo.x); FFMA2(ao0, x0.y, wo.y);
                    FFMA2(ao1, x1.x, wo.x); FFMA2(ao1, x1.y, wo.y);
                    FFMA2(ao2, x2.x, wo.x); FFMA2(ao2, x2.y, wo.y);
                    FFMA2(ao3, x3.x, wo.x); FFMA2(ao3, x3.y, wo.y);
                }
                unsigned long long au0 = 0, au1 = 0, au2 = 0, au3 = 0;
                #pragma unroll 2
                for (int k4 = 0; k4 < 64; k4++) {
                    ulonglong2 wu = *(const ulonglong2*)&Wu4[k4 * 128 + lane * 4];
                    ulonglong2 x0 = *(const ulonglong2*)&hbw[k4 * 4];
                    ulonglong2 x1 = *(const ulonglong2*)&hbw[256 + k4 * 4];
                    ulonglong2 x2 = *(const ulonglong2*)&hbw[512 + k4 * 4];
                    ulonglong2 x3 = *(const ulonglong2*)&hbw[768 + k4 * 4];
                    FFMA2(au0, x0.x, wu.x); FFMA2(au0, x0.y, wu.y);
                    FFMA2(au1, x1.x, wu.x); FFMA2(au1, x1.y, wu.y);
                    FFMA2(au2, x2.x, wu.x); FFMA2(au2, x2.y, wu.y);
                    FFMA2(au3, x3.x, wu.x); FFMA2(au3, x3.y, wu.y);
                }
                float hv[4];
                #pragma unroll
                for (int m = 0; m < 4; m++) hv[m] = 0.0f;
                {
                    size_t nx = (size_t)nid[0] * Hv + J;
                    float iv = sigf(g_proj[0][nx] + pairsum(ai0));
                    float ov = sigf(g_proj[2][nx] + pairsum(ao0));
                    float uv = __tanhf(g_proj[3][nx] + pairsum(au0));
                    float cn = iv * uv + fcv[0];
                    g_c[nx] = cn;
                    hv[0] = ov * __tanhf(cn);
                    g_h[nx] = hv[0];
                }
                if (nid[1] >= 0) {
                    size_t nx = (size_t)nid[1] * Hv + J;
                    float iv = sigf(g_proj[0][nx] + pairsum(ai1));
                    float ov = sigf(g_proj[2][nx] + pairsum(ao1));
                    float uv = __tanhf(g_proj[3][nx] + pairsum(au1));
                    float cn = iv * uv + fcv[1];
                    g_c[nx] = cn;
                    hv[1] = ov * __tanhf(cn);
                    g_h[nx] = hv[1];
                }
                if (nid[2] >= 0) {
                    size_t nx = (size_t)nid[2] * Hv + J;
                    float iv = sigf(g_proj[0][nx] + pairsum(ai2));
                    float ov = sigf(g_proj[2][nx] + pairsum(ao2));
                    float uv = __tanhf(g_proj[3][nx] + pairsum(au2));
                    float cn = iv * uv + fcv[2];
                    g_c[nx] = cn;
                    hv[2] = ov * __tanhf(cn);
                    g_h[nx] = hv[2];
                }
                if (nid[3] >= 0) {
                    size_t nx = (size_t)nid[3] * Hv + J;
                    float iv = sigf(g_proj[0][nx] + pairsum(ai3));
                    float ov = sigf(g_proj[2][nx] + pairsum(ao3));
                    float uv = __tanhf(g_proj[3][nx] + pairsum(au3));
                    float cn = iv * uv + fcv[3];
                    g_c[nx] = cn;
                    hv[3] = ov * __tanhf(cn);
                    g_h[nx] = hv[3];
                }
                if (lev < tmax) {
                    pfh_chunk(Wf, hbw, lane, g, nid[0], nid[1], nid[2], nid[3],
                              hv[0], hv[1], hv[2], hv[3]);
                }
            }
            __syncthreads();
            if (tid == 0) st_rel(&g_lflag[(b * NLEVF + lev) * 8 + g], 1u);
        }
    }

    // ---- pooling (column-local) + head -----------------------------------
    __syncthreads();
    {
        float m = -1e30f;
        for (int s2 = warp; s2 < Sv; s2 += 16)
            m = fmaxf(m, g_h[(size_t)(b * Sv + s2) * Hv + J]);
        scratch[warp * 32 + lane] = m;
        __syncthreads();
        if (tid < 32) {
            float mm = scratch[tid];
            #pragma unroll
            for (int r = 1; r < 16; r++) mm = fmaxf(mm, scratch[r * 32 + tid]);
            g_pooled[b * Hv + g * 32 + tid] = mm;
        }
        __syncthreads();
        if (tid == 0) red_add_rel(&g_pdone[b * 32], 1u);
    }
    if (g == 0) {
        if (tid == 0) { while (ld_acq(&g_pdone[b * 32]) < 8u) { } }
        __syncthreads();
        if (warp < Lv) {
            float acc = 0.0f;
            for (int k = lane; k < Hv; k += 32)
                acc += g_pooled[b * Hv + k] * W_out[k * Lv + warp];
            #pragma unroll
            for (int off = 16; off; off >>= 1)
                acc += __shfl_down_sync(0xFFFFFFFFu, acc, off);
            if (lane == 0) out[b * Lv + warp] = acc + b_out[warp];
        }
    }
}

// ---------------- launch --------------------------------------------------
extern "C" void kernel_launch(void* const* d_in, const int* in_sizes, int n_in,
                              void* d_out, int out_size) {
    const int s = (n_in >= 22) ? 1 : 0;   // robust to n_levels scalar presence
    const int* xs          = (const int*)d_in[0];
    const int* rels        = (const int*)d_in[1];
    const int* child_idx   = (const int*)d_in[2];
    const int* parent_idx  = (const int*)d_in[3];
    const int* node_height = (const int*)d_in[4];
    const float* emb_W = (const float*)d_in[5 + s];
    const float* rel_W = (const float*)d_in[6 + s];
    const float* W_ix  = (const float*)d_in[7 + s];
    const float* b_ix  = (const float*)d_in[8 + s];
    const float* W_ih  = (const float*)d_in[9 + s];
    const float* b_ih  = (const float*)d_in[10 + s];
    const float* W_fx  = (const float*)d_in[11 + s];
    const float* b_fx  = (const float*)d_in[12 + s];
    const float* W_fh  = (const float*)d_in[13 + s];
    const float* b_fh  = (const float*)d_in[14 + s];
    const float* W_ox  = (const float*)d_in[15 + s];
    const float* W_oh  = (const float*)d_in[16 + s];
    const float* W_ux  = (const float*)d_in[17 + s];
    const float* W_uh  = (const float*)d_in[18 + s];
    const float* W_out = (const float*)d_in[19 + s];
    const float* b_out = (const float*)d_in[20 + s];
    float* out = (float*)d_out;

    cudaFuncSetAttribute(main_kernel, cudaFuncAttributeMaxDynamicSharedMemorySize, SMEM_BYTES);

    setup_kernel<<<1, 1024>>>(child_idx, parent_idx, node_height);
    main_kernel<<<NCTA, NTHR, SMEM_BYTES>>>(xs, rels, emb_W, rel_W,
                                            W_ix, b_ix, W_ih, b_ih,
                                            W_fx, b_fx, W_fh, b_fh,
                                            W_ox, W_oh, W_ux, W_uh,
                                            W_out, b_out, out);
}

// round 9
// speedup vs baseline: 1.4343x; 1.2524x over previous
#include <cuda_runtime.h>

#define Nn   2048      // B*S
#define Bv   16
#define Sv   128
#define Hv   256
#define DINv 256
#define DEv  192
#define DRv  64
#define Ev   2032      // B*(S-1)
#define Lv   12
#define NCTA 128       // 16 trees x 8 column groups
#define NTHR 512
#define NLEVF 24
#define SMEM_BYTES 196608   // 48K floats: 32K weights + 16K scratch

// packed fp32x2 FMA (sm_103a FFMA2)
#define FFMA2(acc, a, b) asm("fma.rn.f32x2 %0, %1, %2, %0;" : "+l"(acc) : "l"(a), "l"(b))
#define TEAM_BAR(t) asm volatile("bar.sync %0, %1;" :: "r"((t) + 1), "r"(128) : "memory")

__device__ __forceinline__ float pairsum(unsigned long long v) {
    float lo, hi;
    asm("mov.b64 {%0, %1}, %2;" : "=f"(lo), "=f"(hi) : "l"(v));
    return lo + hi;
}

// ---------------- device scratch (no allocations allowed) ----------------
__device__ float g_proj[4][Nn * Hv];   // i(+bi+bih), f(+bf+bfh), o, u  (column-local)
__device__ float g_h[Nn * Hv];
__device__ float g_c[Nn * Hv];         // column-local
__device__ float g_fh[Nn * Hv];        // W_fh . h  (column-local)
__device__ float g_pooled[Bv * Hv];
__device__ int   g_coff[Nn + 1];
__device__ int   g_children[Ev];
__device__ int   g_tl_off[512];        // [16][32] per-tree level offsets
__device__ int   g_tl_nodes[Nn];
__device__ int   g_tmax[Bv];
__device__ unsigned g_lflag[Bv * NLEVF * 8];  // per-tree per-level per-CTA flag
__device__ unsigned g_pdone[Bv * 32];

// fence-free release/acquire primitives (no CCTL.IVALL -> L1 stays warm)
__device__ __forceinline__ unsigned ld_acq(unsigned* p) {
    unsigned v;
    asm volatile("ld.acquire.gpu.global.u32 %0, [%1];" : "=r"(v) : "l"(p) : "memory");
    return v;
}
__device__ __forceinline__ void st_rel(unsigned* p, unsigned v) {
    asm volatile("st.release.gpu.global.u32 [%0], %1;" :: "l"(p), "r"(v) : "memory");
}
__device__ __forceinline__ void red_add_rel(unsigned* p, unsigned v) {
    asm volatile("red.release.gpu.global.add.u32 [%0], %1;" :: "l"(p), "r"(v) : "memory");
}

__device__ __forceinline__ float sigf(float x) {
    return 1.0f / (1.0f + __expf(-x));
}

// ---------------- setup: CSR + per-tree level buckets + flag reset --------
__global__ void setup_kernel(const int* __restrict__ child_idx,
                             const int* __restrict__ parent_idx,
                             const int* __restrict__ node_height) {
    __shared__ int cnt[Nn];
    __shared__ int psm[Ev];
    __shared__ int hsm[Nn];
    __shared__ int part[256];
    __shared__ int lvl[512];
    __shared__ int lfill[512];
    __shared__ int loff[512];
    const int tid = threadIdx.x;               // 1024 threads
    for (int i = tid; i < Nn; i += 1024) { cnt[i] = 0; hsm[i] = node_height[i]; }
    for (int i = tid; i < Ev; i += 1024) psm[i] = parent_idx[i];
    for (int i = tid; i < 512; i += 1024) { lvl[i] = 0; lfill[i] = 0; }
    for (int i = tid; i < Bv * NLEVF * 8; i += 1024) g_lflag[i] = 0u;
    if (tid < Bv) g_pdone[tid * 32] = 0u;
    __syncthreads();
    for (int e = tid; e < Ev; e += 1024) atomicAdd(&cnt[psm[e]], 1);
    for (int n = tid; n < Nn; n += 1024) atomicAdd(&lvl[(n >> 7) * 32 + hsm[n]], 1);
    __syncthreads();
    if (tid < 256) { int s = 0; for (int i = 0; i < 8; i++) s += cnt[tid * 8 + i]; part[tid] = s; }
    __syncthreads();
    if (tid == 0) {
        int run = 0;
        for (int i = 0; i < 256; i++) { int v = part[i]; part[i] = run; run += v; }
    }
    if (tid < 16) {                            // per-tree level prefix + maxlev
        int run = 0, mx = 1;
        for (int l = 0; l < 32; l++) {
            loff[tid * 32 + l] = tid * 128 + run;
            if (lvl[tid * 32 + l] > 0) mx = l;
            run += lvl[tid * 32 + l];
        }
        g_tmax[tid] = mx;
    }
    __syncthreads();
    for (int i = tid; i < 512; i += 1024) g_tl_off[i] = loff[i];
    if (tid < 256) {
        int run = part[tid];
        for (int i = 0; i < 8; i++) { int idx = tid * 8 + i; g_coff[idx] = run; run += cnt[idx]; }
        if (tid == 255) g_coff[Nn] = run;
    }
    __syncthreads();
    // deterministic CSR scatter: rank = #earlier same-parent edges (same batch)
    for (int e = tid; e < Ev; e += 1024) {
        int p = psm[e];
        int bstart = (e / (Sv - 1)) * (Sv - 1);
        int rank = 0;
        for (int e2 = bstart; e2 < e; e2++) rank += (psm[e2] == p);
        g_children[g_coff[p] + rank] = child_idx[e];
    }
    // per-tree level bucket fill (intra-level order numerically irrelevant)
    for (int n = tid; n < Nn; n += 1024) {
        int key = (n >> 7) * 32 + hsm[n];
        int r = atomicAdd(&lfill[key], 1);
        g_tl_nodes[loff[key] + r] = n;
    }
}

// ---------------- persistent kernel: per-tree, K-split teams --------------
__global__ void __launch_bounds__(NTHR, 1)
main_kernel(const int* __restrict__ xs, const int* __restrict__ rels,
            const float* __restrict__ emb_W, const float* __restrict__ rel_W,
            const float* __restrict__ W_ix, const float* __restrict__ b_ix,
            const float* __restrict__ W_ih, const float* __restrict__ b_ih,
            const float* __restrict__ W_fx, const float* __restrict__ b_fx,
            const float* __restrict__ W_fh, const float* __restrict__ b_fh,
            const float* __restrict__ W_ox, const float* __restrict__ W_oh,
            const float* __restrict__ W_ux, const float* __restrict__ W_uh,
            const float* __restrict__ W_out, const float* __restrict__ b_out,
            float* __restrict__ out) {
    extern __shared__ float sm[];
    float* Wi4 = sm;                  // col-slice layout [(k>>2)*128 + col*4 + (k&3)]
    float* Wo4 = sm + 8192;
    float* Wu4 = sm + 16384;
    float* Wf4 = sm + 24576;
    float* scratch = sm + 32768;      // 16384 floats

    const int tid  = threadIdx.x;
    const int lane = tid & 31;
    const int warp = tid >> 5;
    const int team = warp >> 2;       // 4 teams of 4 warps
    const int sub  = warp & 3;        // K-slice within team
    const int blk  = blockIdx.x;
    const int b    = blk >> 3;        // tree id
    const int g    = blk & 7;         // column group
    const int J    = g * 32 + lane;

    // team-private buffers (4096 floats per team)
    float* tb   = scratch + team * 4096;
    float* xbuf = tb;                 // 2 x 256 (h_sum slices, dbl-buffered)
    float* fhp  = tb + 512;           // 2 x 128 fh partials
    float* gi   = tb + 768;           // 2 x 128 i partials
    float* go   = tb + 1024;          // 2 x 128 o partials
    float* gu   = tb + 1280;          // 2 x 128 u partials
    float* gf   = tb + 1536;          // 2 x 128 fc partials

    // ---- load INPUT weight col-slices ------------------------------------
    {
        const int jb2 = g * 32;
        for (int it = 0; it < 16; it++) {
            int k = it * 16 + (tid >> 5);
            int col = tid & 31;
            int didx = (k >> 2) * 128 + col * 4 + (k & 3);
            int sidx = k * Hv + jb2 + col;
            Wi4[didx] = W_ix[sidx];
            Wo4[didx] = W_ox[sidx];
            Wu4[didx] = W_ux[sidx];
            Wf4[didx] = W_fx[sidx];
        }
    }
    const float bi = b_ix[J] + b_ih[J];
    const float bf = b_fx[J] + b_fh[J];
    __syncthreads();

    // ---- P1: all 4 projections, columns J, this tree's 128 nodes ---------
    {
        float* xw = scratch + warp * 1024;
        for (int t = 0; t < 8; t++) {
            int n = b * Sv + warp + t * 16;
            __syncwarp();
            const float4* er = (const float4*)(emb_W + (size_t)xs[n] * DEv);
            const float4* rr = (const float4*)(rel_W + (size_t)rels[n] * DRv);
            float4 a = er[lane];
            float4 bb = (lane < 16) ? er[lane + 32] : rr[lane - 16];
            ((float4*)xw)[lane] = a; ((float4*)xw)[lane + 32] = bb;
            __syncwarp();
            unsigned long long aiX = 0, aiY = 0, aoX = 0, aoY = 0;
            unsigned long long auX = 0, auY = 0, afX = 0, afY = 0;
            #pragma unroll 4
            for (int k4 = 0; k4 < 64; k4++) {
                ulonglong2 xv = *(const ulonglong2*)&xw[k4 * 4];
                ulonglong2 wi = *(const ulonglong2*)&Wi4[k4 * 128 + lane * 4];
                ulonglong2 wo = *(const ulonglong2*)&Wo4[k4 * 128 + lane * 4];
                ulonglong2 wu = *(const ulonglong2*)&Wu4[k4 * 128 + lane * 4];
                ulonglong2 wf = *(const ulonglong2*)&Wf4[k4 * 128 + lane * 4];
                FFMA2(aiX, xv.x, wi.x); FFMA2(aiY, xv.y, wi.y);
                FFMA2(aoX, xv.x, wo.x); FFMA2(aoY, xv.y, wo.y);
                FFMA2(auX, xv.x, wu.x); FFMA2(auY, xv.y, wu.y);
                FFMA2(afX, xv.x, wf.x); FFMA2(afY, xv.y, wf.y);
            }
            size_t nx = (size_t)n * Hv + J;
            g_proj[0][nx] = pairsum(aiX) + pairsum(aiY) + bi;
            g_proj[1][nx] = pairsum(afX) + pairsum(afY) + bf;
            g_proj[2][nx] = pairsum(aoX) + pairsum(aoY);
            g_proj[3][nx] = pairsum(auX) + pairsum(auY);
        }
    }
    __syncthreads();

    // ---- reload RECURRENT weight col-slices ------------------------------
    {
        const int jb2 = g * 32;
        for (int it = 0; it < 16; it++) {
            int k = it * 16 + (tid >> 5);
            int col = tid & 31;
            int didx = (k >> 2) * 128 + col * 4 + (k & 3);
            int sidx = k * Hv + jb2 + col;
            Wi4[didx] = W_ih[sidx];
            Wo4[didx] = W_oh[sidx];
            Wu4[didx] = W_uh[sidx];
            Wf4[didx] = W_fh[sidx];
        }
    }
    __syncthreads();

    // ---- level 0 (leaves): elementwise -----------------------------------
    {
        int lb = g_tl_off[b * 32];
        int le = g_tl_off[b * 32 + 1];
        for (int idx = lb + warp; idx < le; idx += 16) {
            int n = g_tl_nodes[idx];
            size_t nx = (size_t)n * Hv + J;
            float iv = sigf(g_proj[0][nx]);
            float ov = sigf(g_proj[2][nx]);
            float uv = __tanhf(g_proj[3][nx]);
            float cv = iv * uv;
            g_c[nx] = cv;
            g_h[nx] = ov * __tanhf(cv);
        }
    }
    __syncthreads();
    if (tid == 0) st_rel(&g_lflag[(b * NLEVF + 0) * 8 + g], 1u);

    // ---- bottom-up levels: K-split teams, one flag per level -------------
    {
        const int tmax = g_tmax[b];
        for (int lev = 1; lev <= tmax; lev++) {
            // one-hop wait: all 8 CTAs of my tree published level lev-1
            if (warp == 0) {
                unsigned* fp = &g_lflag[(b * NLEVF + lev - 1) * 8 + (lane & 7)];
                for (;;) {
                    unsigned d = (lane < 8) ? ld_acq(fp) : 1u;
                    if (__all_sync(0xFFFFFFFFu, d != 0u)) break;
                }
            }
            __syncthreads();

            // (a) fh-phase: fh = W_fh . h for nodes of height lev-1
            {
                int pbase = g_tl_off[b * 32 + (lev - 1)];
                int pcnt  = g_tl_off[b * 32 + lev] - pbase;
                int par = 0;
                for (int idx = team; idx < pcnt; idx += 4) {
                    int n = g_tl_nodes[pbase + idx];
                    const float* hrow = g_h + (size_t)n * Hv;
                    unsigned long long aX = 0, aY = 0;
                    #pragma unroll
                    for (int q = 0; q < 16; q++) {
                        int kk = sub * 16 + q;
                        ulonglong2 wf = *(const ulonglong2*)&Wf4[kk * 128 + lane * 4];
                        ulonglong2 xv = *(const ulonglong2*)(hrow + kk * 4);
                        FFMA2(aX, xv.x, wf.x); FFMA2(aY, xv.y, wf.y);
                    }
                    fhp[par * 128 + sub * 32 + lane] = pairsum(aX) + pairsum(aY);
                    TEAM_BAR(team);
                    if (sub == 0) {
                        const float* p = &fhp[par * 128];
                        g_fh[(size_t)n * Hv + J] =
                            (p[lane] + p[32 + lane]) + (p[64 + lane] + p[96 + lane]);
                    }
                    par ^= 1;
                }
            }
            __syncthreads();

            // (b) gate-phase: nodes of height lev (4 warps per node, K-split)
            {
                int base = g_tl_off[b * 32 + lev];
                int cntl = g_tl_off[b * 32 + lev + 1] - base;
                int par = 0;
                const int ko = sub * 64 + lane * 2;   // my 2 h_sum components
                for (int idx = team; idx < cntl; idx += 4) {
                    int n = g_tl_nodes[base + idx];
                    int cs = g_coff[n], ce = g_coff[n + 1];
                    float fx = g_proj[1][(size_t)n * Hv + J];
                    float2 hs = make_float2(0.0f, 0.0f);
                    for (int ci = cs; ci < ce; ci++) {
                        int ch = g_children[ci];
                        float2 v = *(const float2*)(g_h + (size_t)ch * Hv + ko);
                        hs.x += v.x; hs.y += v.y;
                    }
                    float fc = 0.0f;
                    for (int ci = cs + sub; ci < ce; ci += 4) {
                        int ch = g_children[ci];
                        float fhv = g_fh[(size_t)ch * Hv + J];
                        float cch = g_c[(size_t)ch * Hv + J];
                        fc += sigf(fhv + fx) * cch;
                    }
                    *(float2*)&xbuf[par * 256 + ko] = hs;
                    gf[par * 128 + sub * 32 + lane] = fc;
                    __syncwarp();      // my slice of xbuf written by my warp only
                    unsigned long long ai = 0, aj = 0, ao = 0, ap = 0, au = 0, av = 0;
                    #pragma unroll
                    for (int q = 0; q < 16; q++) {
                        int kk = sub * 16 + q;
                        ulonglong2 xv = *(const ulonglong2*)&xbuf[par * 256 + kk * 4];
                        ulonglong2 wi = *(const ulonglong2*)&Wi4[kk * 128 + lane * 4];
                        ulonglong2 wo = *(const ulonglong2*)&Wo4[kk * 128 + lane * 4];
                        ulonglong2 wu = *(const ulonglong2*)&Wu4[kk * 128 + lane * 4];
                        FFMA2(ai, xv.x, wi.x); FFMA2(aj, xv.y, wi.y);
                        FFMA2(ao, xv.x, wo.x); FFMA2(ap, xv.y, wo.y);
                        FFMA2(au, xv.x, wu.x); FFMA2(av, xv.y, wu.y);
                    }
                    gi[par * 128 + sub * 32 + lane] = pairsum(ai) + pairsum(aj);
                    go[par * 128 + sub * 32 + lane] = pairsum(ao) + pairsum(ap);
                    gu[par * 128 + sub * 32 + lane] = pairsum(au) + pairsum(av);
                    TEAM_BAR(team);
                    if (sub == 0) {
                        const float* pi = &gi[par * 128];
                        const float* po = &go[par * 128];
                        const float* pu = &gu[par * 128];
                        const float* pf = &gf[par * 128];
                        float si = (pi[lane] + pi[32 + lane]) + (pi[64 + lane] + pi[96 + lane]);
                        float so = (po[lane] + po[32 + lane]) + (po[64 + lane] + po[96 + lane]);
                        float su = (pu[lane] + pu[32 + lane]) + (pu[64 + lane] + pu[96 + lane]);
                        float sf = (pf[lane] + pf[32 + lane]) + (pf[64 + lane] + pf[96 + lane]);
                        size_t nx = (size_t)n * Hv + J;
                        float iv = sigf(g_proj[0][nx] + si);
                        float ov = sigf(g_proj[2][nx] + so);
                        float uv = __tanhf(g_proj[3][nx] + su);
                        float cn = iv * uv + sf;
                        g_c[nx] = cn;
                        g_h[nx] = ov * __tanhf(cn);
                    }
                    par ^= 1;
                }
            }
            __syncthreads();
            if (tid == 0) st_rel(&g_lflag[(b * NLEVF + lev) * 8 + g], 1u);
        }
    }

    // ---- pooling (column-local) + head -----------------------------------
    __syncthreads();
    {
        float m = -1e30f;
        for (int s2 = warp; s2 < Sv; s2 += 16)
            m = fmaxf(m, g_h[(size_t)(b * Sv + s2) * Hv + J]);
        scratch[warp * 32 + lane] = m;
        __syncthreads();
        if (tid < 32) {
            float mm = scratch[tid];
            #pragma unroll
            for (int r = 1; r < 16; r++) mm = fmaxf(mm, scratch[r * 32 + tid]);
            g_pooled[b * Hv + g * 32 + tid] = mm;
        }
        __syncthreads();
        if (tid == 0) red_add_rel(&g_pdone[b * 32], 1u);
    }
    if (g == 0) {
        if (tid == 0) { while (ld_acq(&g_pdone[b * 32]) < 8u) { } }
        __syncthreads();
        if (warp < Lv) {
            float acc = 0.0f;
            for (int k = lane; k < Hv; k += 32)
                acc += g_pooled[b * Hv + k] * W_out[k * Lv + warp];
            #pragma unroll
            for (int off = 16; off; off >>= 1)
                acc += __shfl_down_sync(0xFFFFFFFFu, acc, off);
            if (lane == 0) out[b * Lv + warp] = acc + b_out[warp];
        }
    }
}

// ---------------- launch --------------------------------------------------
extern "C" void kernel_launch(void* const* d_in, const int* in_sizes, int n_in,
                              void* d_out, int out_size) {
    const int s = (n_in >= 22) ? 1 : 0;   // robust to n_levels scalar presence
    const int* xs          = (const int*)d_in[0];
    const int* rels        = (const int*)d_in[1];
    const int* child_idx   = (const int*)d_in[2];
    const int* parent_idx  = (const int*)d_in[3];
    const int* node_height = (const int*)d_in[4];
    const float* emb_W = (const float*)d_in[5 + s];
    const float* rel_W = (const float*)d_in[6 + s];
    const float* W_ix  = (const float*)d_in[7 + s];
    const float* b_ix  = (const float*)d_in[8 + s];
    const float* W_ih  = (const float*)d_in[9 + s];
    const float* b_ih  = (const float*)d_in[10 + s];
    const float* W_fx  = (const float*)d_in[11 + s];
    const float* b_fx  = (const float*)d_in[12 + s];
    const float* W_fh  = (const float*)d_in[13 + s];
    const float* b_fh  = (const float*)d_in[14 + s];
    const float* W_ox  = (const float*)d_in[15 + s];
    const float* W_oh  = (const float*)d_in[16 + s];
    const float* W_ux  = (const float*)d_in[17 + s];
    const float* W_uh  = (const float*)d_in[18 + s];
    const float* W_out = (const float*)d_in[19 + s];
    const float* b_out = (const float*)d_in[20 + s];
    float* out = (float*)d_out;

    cudaFuncSetAttribute(main_kernel, cudaFuncAttributeMaxDynamicSharedMemorySize, SMEM_BYTES);

    setup_kernel<<<1, 1024>>>(child_idx, parent_idx, node_height);
    main_kernel<<<NCTA, NTHR, SMEM_BYTES>>>(xs, rels, emb_W, rel_W,
                                            W_ix, b_ix, W_ih, b_ih,
                                            W_fx, b_fx, W_fh, b_fh,
                                            W_ox, W_oh, W_ux, W_uh,
                                            W_out, b_out, out);
}

// round 10
// speedup vs baseline: 1.5214x; 1.0607x over previous
#include <cuda_runtime.h>

#define Nn   2048      // B*S
#define Bv   16
#define Sv   128
#define Hv   256
#define DINv 256
#define DEv  192
#define DRv  64
#define Ev   2032      // B*(S-1)
#define Lv   12
#define NCTA 128       // 16 trees x 8 column groups
#define NTHR 512
#define NLEVF 24
#define SMEM_BYTES 149504   // 36864 floats (weights+scratch) + 512 ints meta

// packed fp32x2 FMA (sm_103a FFMA2)
#define FFMA2(acc, a, b) asm("fma.rn.f32x2 %0, %1, %2, %0;" : "+l"(acc) : "l"(a), "l"(b))

__device__ __forceinline__ float pairsum(unsigned long long v) {
    float lo, hi;
    asm("mov.b64 {%0, %1}, %2;" : "=f"(lo), "=f"(hi) : "l"(v));
    return lo + hi;
}

// ---------------- device scratch (no allocations allowed) ----------------
__device__ float g_proj[4][Nn * Hv];   // i(+bi+bih), f(+bf+bfh), o, u  (column-local)
__device__ float g_h[Nn * Hv];
__device__ float g_c[Nn * Hv];         // column-local
__device__ float g_fh[Nn * Hv];        // W_fh . h  (column-local)
__device__ float g_pooled[Bv * Hv];
__device__ int   g_coff[Nn + 1];
__device__ int   g_children[Ev];
__device__ int   g_tl_off[512];        // [16][32] per-tree level offsets
__device__ int   g_tl_nodes[Nn];
__device__ int   g_tmax[Bv];
__device__ unsigned g_lflag[Bv * NLEVF * 8];  // per-tree per-level per-CTA flag
__device__ unsigned g_pdone[Bv * 32];

// fence-free release/acquire primitives (no CCTL.IVALL -> L1 stays warm)
__device__ __forceinline__ unsigned ld_acq(unsigned* p) {
    unsigned v;
    asm volatile("ld.acquire.gpu.global.u32 %0, [%1];" : "=r"(v) : "l"(p) : "memory");
    return v;
}
__device__ __forceinline__ void st_rel(unsigned* p, unsigned v) {
    asm volatile("st.release.gpu.global.u32 [%0], %1;" :: "l"(p), "r"(v) : "memory");
}
__device__ __forceinline__ void red_add_rel(unsigned* p, unsigned v) {
    asm volatile("red.release.gpu.global.add.u32 [%0], %1;" :: "l"(p), "r"(v) : "memory");
}

__device__ __forceinline__ float sigf(float x) {
    return 1.0f / (1.0f + __expf(-x));
}

// ---------------- setup: CSR + per-tree level buckets + flag reset --------
__global__ void setup_kernel(const int* __restrict__ child_idx,
                             const int* __restrict__ parent_idx,
                             const int* __restrict__ node_height) {
    __shared__ int cnt[Nn];
    __shared__ int psm[Ev];
    __shared__ int hsm[Nn];
    __shared__ int part[256];
    __shared__ int lvl[512];
    __shared__ int lfill[512];
    __shared__ int loff[512];
    const int tid = threadIdx.x;               // 1024 threads
    for (int i = tid; i < Nn; i += 1024) { cnt[i] = 0; hsm[i] = node_height[i]; }
    for (int i = tid; i < Ev; i += 1024) psm[i] = parent_idx[i];
    for (int i = tid; i < 512; i += 1024) { lvl[i] = 0; lfill[i] = 0; }
    for (int i = tid; i < Bv * NLEVF * 8; i += 1024) g_lflag[i] = 0u;
    if (tid < Bv) g_pdone[tid * 32] = 0u;
    __syncthreads();
    for (int e = tid; e < Ev; e += 1024) atomicAdd(&cnt[psm[e]], 1);
    for (int n = tid; n < Nn; n += 1024) atomicAdd(&lvl[(n >> 7) * 32 + hsm[n]], 1);
    __syncthreads();
    if (tid < 256) { int s = 0; for (int i = 0; i < 8; i++) s += cnt[tid * 8 + i]; part[tid] = s; }
    __syncthreads();
    if (tid == 0) {
        int run = 0;
        for (int i = 0; i < 256; i++) { int v = part[i]; part[i] = run; run += v; }
    }
    if (tid < 16) {                            // per-tree level prefix + maxlev
        int run = 0, mx = 1;
        for (int l = 0; l < 32; l++) {
            loff[tid * 32 + l] = tid * 128 + run;
            if (lvl[tid * 32 + l] > 0) mx = l;
            run += lvl[tid * 32 + l];
        }
        g_tmax[tid] = mx;
    }
    __syncthreads();
    for (int i = tid; i < 512; i += 1024) g_tl_off[i] = loff[i];
    if (tid < 256) {
        int run = part[tid];
        for (int i = 0; i < 8; i++) { int idx = tid * 8 + i; g_coff[idx] = run; run += cnt[idx]; }
        if (tid == 255) g_coff[Nn] = run;
    }
    __syncthreads();
    // deterministic CSR scatter: rank = #earlier same-parent edges (same batch)
    for (int e = tid; e < Ev; e += 1024) {
        int p = psm[e];
        int bstart = (e / (Sv - 1)) * (Sv - 1);
        int rank = 0;
        for (int e2 = bstart; e2 < e; e2++) rank += (psm[e2] == p);
        g_children[g_coff[p] + rank] = child_idx[e];
    }
    // per-tree level bucket fill (intra-level order numerically irrelevant)
    for (int n = tid; n < Nn; n += 1024) {
        int key = (n >> 7) * 32 + hsm[n];
        int r = atomicAdd(&lfill[key], 1);
        g_tl_nodes[loff[key] + r] = n;
    }
}

// ---------------- persistent kernel: per-tree, m=1 latency path -----------
__global__ void __launch_bounds__(NTHR, 1)
main_kernel(const int* __restrict__ xs, const int* __restrict__ rels,
            const float* __restrict__ emb_W, const float* __restrict__ rel_W,
            const float* __restrict__ W_ix, const float* __restrict__ b_ix,
            const float* __restrict__ W_ih, const float* __restrict__ b_ih,
            const float* __restrict__ W_fx, const float* __restrict__ b_fx,
            const float* __restrict__ W_fh, const float* __restrict__ b_fh,
            const float* __restrict__ W_ox, const float* __restrict__ W_oh,
            const float* __restrict__ W_ux, const float* __restrict__ W_uh,
            const float* __restrict__ W_out, const float* __restrict__ b_out,
            float* __restrict__ out) {
    extern __shared__ float sm[];
    float* Wi4 = sm;                  // col-slice layout [(k>>2)*128 + col*4 + (k&3)]
    float* Wo4 = sm + 8192;
    float* Wu4 = sm + 16384;
    float* Wf4 = sm + 24576;
    float* scratch = sm + 32768;      // 4096 floats = 16 warps x 256
    int*   meta = (int*)(sm + 36864); // 512 ints
    int* sm_tloff = meta;             // 33 (only 0..22 used)
    int* sm_tln   = meta + 33;        // 128 node ids (global)
    int* sm_coff  = meta + 161;       // 129, rebased
    int* sm_child = meta + 290;       // <=127 child node ids (global)

    const int tid  = threadIdx.x;
    const int lane = tid & 31;
    const int warp = tid >> 5;
    const int blk  = blockIdx.x;
    const int b    = blk >> 3;        // tree id
    const int g    = blk & 7;         // column group
    const int J    = g * 32 + lane;
    float* xw = scratch + warp * 256; // my warp's 256-float staging buffer

    // ---- phase 0: weights (input-side) + tree metadata -> smem -----------
    {
        const int jb2 = g * 32;
        for (int it = 0; it < 16; it++) {
            int k = it * 16 + (tid >> 5);
            int col = tid & 31;
            int didx = (k >> 2) * 128 + col * 4 + (k & 3);
            int sidx = k * Hv + jb2 + col;
            Wi4[didx] = W_ix[sidx];
            Wo4[didx] = W_ox[sidx];
            Wu4[didx] = W_ux[sidx];
            Wf4[didx] = W_fx[sidx];
        }
        if (tid < 32) sm_tloff[tid] = g_tl_off[b * 32 + tid] - b * 128;
        if (tid >= 32 && tid < 160) sm_tln[tid - 32] = g_tl_nodes[b * 128 + (tid - 32)];
        int cbase = g_coff[b * 128];
        int cend  = g_coff[b * 128 + 128];
        if (tid >= 160 && tid < 289) sm_coff[tid - 160] = g_coff[b * 128 + (tid - 160)] - cbase;
        for (int i = tid; i < cend - cbase; i += NTHR) sm_child[i] = g_children[cbase + i];
    }
    const float bi = b_ix[J] + b_ih[J];
    const float bf = b_fx[J] + b_fh[J];
    __syncthreads();

    // ---- P1: all 4 projections, columns J, this tree's 128 nodes ---------
    {
        for (int t = 0; t < 8; t++) {
            int n = b * Sv + warp + t * 16;
            __syncwarp();
            const float4* er = (const float4*)(emb_W + (size_t)xs[n] * DEv);
            const float4* rr = (const float4*)(rel_W + (size_t)rels[n] * DRv);
            float4 a = er[lane];
            float4 bb = (lane < 16) ? er[lane + 32] : rr[lane - 16];
            ((float4*)xw)[lane] = a; ((float4*)xw)[lane + 32] = bb;
            __syncwarp();
            unsigned long long aiX = 0, aiY = 0, aoX = 0, aoY = 0;
            unsigned long long auX = 0, auY = 0, afX = 0, afY = 0;
            #pragma unroll 4
            for (int k4 = 0; k4 < 64; k4++) {
                ulonglong2 xv = *(const ulonglong2*)&xw[k4 * 4];
                ulonglong2 wi = *(const ulonglong2*)&Wi4[k4 * 128 + lane * 4];
                ulonglong2 wo = *(const ulonglong2*)&Wo4[k4 * 128 + lane * 4];
                ulonglong2 wu = *(const ulonglong2*)&Wu4[k4 * 128 + lane * 4];
                ulonglong2 wf = *(const ulonglong2*)&Wf4[k4 * 128 + lane * 4];
                FFMA2(aiX, xv.x, wi.x); FFMA2(aiY, xv.y, wi.y);
                FFMA2(aoX, xv.x, wo.x); FFMA2(aoY, xv.y, wo.y);
                FFMA2(auX, xv.x, wu.x); FFMA2(auY, xv.y, wu.y);
                FFMA2(afX, xv.x, wf.x); FFMA2(afY, xv.y, wf.y);
            }
            size_t nx = (size_t)n * Hv + J;
            g_proj[0][nx] = pairsum(aiX) + pairsum(aiY) + bi;
            g_proj[1][nx] = pairsum(afX) + pairsum(afY) + bf;
            g_proj[2][nx] = pairsum(aoX) + pairsum(aoY);
            g_proj[3][nx] = pairsum(auX) + pairsum(auY);
        }
    }
    __syncthreads();

    // ---- reload RECURRENT weight col-slices ------------------------------
    {
        const int jb2 = g * 32;
        for (int it = 0; it < 16; it++) {
            int k = it * 16 + (tid >> 5);
            int col = tid & 31;
            int didx = (k >> 2) * 128 + col * 4 + (k & 3);
            int sidx = k * Hv + jb2 + col;
            Wi4[didx] = W_ih[sidx];
            Wo4[didx] = W_oh[sidx];
            Wu4[didx] = W_uh[sidx];
            Wf4[didx] = W_fh[sidx];
        }
    }
    __syncthreads();

    // ---- level 0 (leaves): elementwise, m=1 ------------------------------
    {
        int lb = sm_tloff[0], le = sm_tloff[1];
        for (int idx = lb + warp; idx < le; idx += 16) {
            int n = sm_tln[idx];
            size_t nx = (size_t)n * Hv + J;
            float iv = sigf(g_proj[0][nx]);
            float ov = sigf(g_proj[2][nx]);
            float uv = __tanhf(g_proj[3][nx]);
            float cv = iv * uv;
            g_c[nx] = cv;
            g_h[nx] = ov * __tanhf(cv);
        }
    }
    __syncthreads();
    if (tid == 0) st_rel(&g_lflag[(b * NLEVF + 0) * 8 + g], 1u);

    // ---- bottom-up levels: m=1 per warp, one flag per level --------------
    {
        const int tmax = g_tmax[b];
        for (int lev = 1; lev <= tmax; lev++) {
            // one-hop wait: all 8 CTAs of my tree published level lev-1
            if (warp == 0) {
                unsigned* fp = &g_lflag[(b * NLEVF + lev - 1) * 8 + (lane & 7)];
                for (;;) {
                    unsigned d = (lane < 8) ? ld_acq(fp) : 1u;
                    if (__all_sync(0xFFFFFFFFu, d != 0u)) break;
                }
            }
            __syncthreads();

            // (a) fh-phase: fh = W_fh . h for nodes of height lev-1 (1/warp)
            {
                int pb = sm_tloff[lev - 1], pe = sm_tloff[lev];
                for (int idx = pb + warp; idx < pe; idx += 16) {
                    int n = sm_tln[idx];
                    const float4* hsrc = (const float4*)(g_h + (size_t)n * Hv);
                    __syncwarp();
                    ((float4*)xw)[lane] = hsrc[lane];
                    ((float4*)xw)[lane + 32] = hsrc[lane + 32];
                    __syncwarp();
                    unsigned long long aX = 0, aY = 0;
                    #pragma unroll 8
                    for (int k4 = 0; k4 < 64; k4++) {
                        ulonglong2 wf = *(const ulonglong2*)&Wf4[k4 * 128 + lane * 4];
                        ulonglong2 xv = *(const ulonglong2*)&xw[k4 * 4];
                        FFMA2(aX, xv.x, wf.x); FFMA2(aY, xv.y, wf.y);
                    }
                    g_fh[(size_t)n * Hv + J] = pairsum(aX) + pairsum(aY);
                }
            }
            __syncthreads();

            // (b) gate-phase: nodes of height lev (1 node per warp)
            {
                int base = sm_tloff[lev], lend = sm_tloff[lev + 1];
                for (int idx = base + warp; idx < lend; idx += 16) {
                    int n = sm_tln[idx];
                    int nloc = n - b * Sv;
                    float fx = g_proj[1][(size_t)n * Hv + J];
                    int cs = sm_coff[nloc], ce = sm_coff[nloc + 1];
                    float4 s0 = make_float4(0, 0, 0, 0), s1 = make_float4(0, 0, 0, 0);
                    float fc = 0.0f;
                    for (int ci = cs; ci < ce; ci++) {
                        int ch = sm_child[ci];
                        const float4* hsrc = (const float4*)(g_h + (size_t)ch * Hv);
                        float4 v0 = hsrc[lane], v1 = hsrc[lane + 32];
                        s0.x += v0.x; s0.y += v0.y; s0.z += v0.z; s0.w += v0.w;
                        s1.x += v1.x; s1.y += v1.y; s1.z += v1.z; s1.w += v1.w;
                        fc += sigf(g_fh[(size_t)ch * Hv + J] + fx)
                              * g_c[(size_t)ch * Hv + J];
                    }
                    __syncwarp();
                    ((float4*)xw)[lane] = s0; ((float4*)xw)[lane + 32] = s1;
                    __syncwarp();
                    unsigned long long ai = 0, aj = 0, ao = 0, ap = 0, au = 0, av = 0;
                    #pragma unroll 4
                    for (int k4 = 0; k4 < 64; k4++) {
                        ulonglong2 xv = *(const ulonglong2*)&xw[k4 * 4];
                        ulonglong2 wi = *(const ulonglong2*)&Wi4[k4 * 128 + lane * 4];
                        ulonglong2 wo = *(const ulonglong2*)&Wo4[k4 * 128 + lane * 4];
                        ulonglong2 wu = *(const ulonglong2*)&Wu4[k4 * 128 + lane * 4];
                        FFMA2(ai, xv.x, wi.x); FFMA2(aj, xv.y, wi.y);
                        FFMA2(ao, xv.x, wo.x); FFMA2(ap, xv.y, wo.y);
                        FFMA2(au, xv.x, wu.x); FFMA2(av, xv.y, wu.y);
                    }
                    size_t nx = (size_t)n * Hv + J;
                    float iv = sigf(g_proj[0][nx] + pairsum(ai) + pairsum(aj));
                    float ov = sigf(g_proj[2][nx] + pairsum(ao) + pairsum(ap));
                    float uv = __tanhf(g_proj[3][nx] + pairsum(au) + pairsum(av));
                    float cn = iv * uv + fc;
                    g_c[nx] = cn;
                    g_h[nx] = ov * __tanhf(cn);
                }
            }
            __syncthreads();
            if (tid == 0) st_rel(&g_lflag[(b * NLEVF + lev) * 8 + g], 1u);
        }
    }

    // ---- pooling (column-local) + head -----------------------------------
    __syncthreads();
    {
        float m = -1e30f;
        for (int s2 = warp; s2 < Sv; s2 += 16)
            m = fmaxf(m, g_h[(size_t)(b * Sv + s2) * Hv + J]);
        scratch[warp * 32 + lane] = m;
        __syncthreads();
        if (tid < 32) {
            float mm = scratch[tid];
            #pragma unroll
            for (int r = 1; r < 16; r++) mm = fmaxf(mm, scratch[r * 32 + tid]);
            g_pooled[b * Hv + g * 32 + tid] = mm;
        }
        __syncthreads();
        if (tid == 0) red_add_rel(&g_pdone[b * 32], 1u);
    }
    if (g == 0) {
        if (tid == 0) { while (ld_acq(&g_pdone[b * 32]) < 8u) { } }
        __syncthreads();
        if (warp < Lv) {
            float acc = 0.0f;
            for (int k = lane; k < Hv; k += 32)
                acc += g_pooled[b * Hv + k] * W_out[k * Lv + warp];
            #pragma unroll
            for (int off = 16; off; off >>= 1)
                acc += __shfl_down_sync(0xFFFFFFFFu, acc, off);
            if (lane == 0) out[b * Lv + warp] = acc + b_out[warp];
        }
    }
}

// ---------------- launch --------------------------------------------------
extern "C" void kernel_launch(void* const* d_in, const int* in_sizes, int n_in,
                              void* d_out, int out_size) {
    const int s = (n_in >= 22) ? 1 : 0;   // robust to n_levels scalar presence
    const int* xs          = (const int*)d_in[0];
    const int* rels        = (const int*)d_in[1];
    const int* child_idx   = (const int*)d_in[2];
    const int* parent_idx  = (const int*)d_in[3];
    const int* node_height = (const int*)d_in[4];
    const float* emb_W = (const float*)d_in[5 + s];
    const float* rel_W = (const float*)d_in[6 + s];
    const float* W_ix  = (const float*)d_in[7 + s];
    const float* b_ix  = (const float*)d_in[8 + s];
    const float* W_ih  = (const float*)d_in[9 + s];
    const float* b_ih  = (const float*)d_in[10 + s];
    const float* W_fx  = (const float*)d_in[11 + s];
    const float* b_fx  = (const float*)d_in[12 + s];
    const float* W_fh  = (const float*)d_in[13 + s];
    const float* b_fh  = (const float*)d_in[14 + s];
    const float* W_ox  = (const float*)d_in[15 + s];
    const float* W_oh  = (const float*)d_in[16 + s];
    const float* W_ux  = (const float*)d_in[17 + s];
    const float* W_uh  = (const float*)d_in[18 + s];
    const float* W_out = (const float*)d_in[19 + s];
    const float* b_out = (const float*)d_in[20 + s];
    float* out = (float*)d_out;

    cudaFuncSetAttribute(main_kernel, cudaFuncAttributeMaxDynamicSharedMemorySize, SMEM_BYTES);

    setup_kernel<<<1, 1024>>>(child_idx, parent_idx, node_height);
    main_kernel<<<NCTA, NTHR, SMEM_BYTES>>>(xs, rels, emb_W, rel_W,
                                            W_ix, b_ix, W_ih, b_ih,
                                            W_fx, b_fx, W_fh, b_fh,
                                            W_ox, W_oh, W_ux, W_uh,
                                            W_out, b_out, out);
}

// round 11
// speedup vs baseline: 2.0522x; 1.3489x over previous
#include <cuda_runtime.h>

#define Nn   2048      // B*S
#define Bv   16
#define Sv   128
#define Hv   256
#define DINv 256
#define DEv  192
#define DRv  64
#define Ev   2032      // B*(S-1)
#define Lv   12
#define NCTA 128       // 16 trees x 8 column groups
#define NTHR 512
#define NLEVF 24
#define SMEM_BYTES 198656   // 32768 wt + 16384 scratch floats + 512 ints meta

// packed fp32x2 FMA (sm_103a FFMA2)
#define FFMA2(acc, a, b) asm("fma.rn.f32x2 %0, %1, %2, %0;" : "+l"(acc) : "l"(a), "l"(b))

__device__ __forceinline__ float pairsum(unsigned long long v) {
    float lo, hi;
    asm("mov.b64 {%0, %1}, %2;" : "=f"(lo), "=f"(hi) : "l"(v));
    return lo + hi;
}

// ---------------- device scratch (no allocations allowed) ----------------
__device__ float g_proj[4][Nn * Hv];   // i(+bi+bih), f(+bf+bfh), o, u  (column-local)
__device__ float g_h[Nn * Hv];
__device__ float g_c[Nn * Hv];         // column-local
__device__ float g_fh[Nn * Hv];        // W_fh . h  (column-local)
__device__ float g_pooled[Bv * Hv];
__device__ int   g_coff[Nn + 1];
__device__ int   g_children[Ev];
__device__ int   g_tl_off[512];        // [16][32] per-tree level offsets
__device__ int   g_tl_nodes[Nn];
__device__ int   g_tmax[Bv];
__device__ unsigned g_lflag[Bv * NLEVF * 8];  // per-tree per-level per-CTA flag
__device__ unsigned g_pdone[Bv * 32];

// fence-free release/acquire primitives (no CCTL.IVALL -> L1 stays warm)
__device__ __forceinline__ unsigned ld_acq(unsigned* p) {
    unsigned v;
    asm volatile("ld.acquire.gpu.global.u32 %0, [%1];" : "=r"(v) : "l"(p) : "memory");
    return v;
}
__device__ __forceinline__ void st_rel(unsigned* p, unsigned v) {
    asm volatile("st.release.gpu.global.u32 [%0], %1;" :: "l"(p), "r"(v) : "memory");
}
__device__ __forceinline__ void red_add_rel(unsigned* p, unsigned v) {
    asm volatile("red.release.gpu.global.add.u32 [%0], %1;" :: "l"(p), "r"(v) : "memory");
}

__device__ __forceinline__ float sigf(float x) {
    return 1.0f / (1.0f + __expf(-x));
}

// ---------------- setup: CSR + per-tree level buckets + flag reset --------
__global__ void setup_kernel(const int* __restrict__ child_idx,
                             const int* __restrict__ parent_idx,
                             const int* __restrict__ node_height) {
    __shared__ int cnt[Nn];
    __shared__ int psm[Ev];
    __shared__ int hsm[Nn];
    __shared__ int part[256];
    __shared__ int lvl[512];
    __shared__ int lfill[512];
    __shared__ int loff[512];
    const int tid = threadIdx.x;               // 1024 threads
    for (int i = tid; i < Nn; i += 1024) { cnt[i] = 0; hsm[i] = node_height[i]; }
    for (int i = tid; i < Ev; i += 1024) psm[i] = parent_idx[i];
    for (int i = tid; i < 512; i += 1024) { lvl[i] = 0; lfill[i] = 0; }
    for (int i = tid; i < Bv * NLEVF * 8; i += 1024) g_lflag[i] = 0u;
    if (tid < Bv) g_pdone[tid * 32] = 0u;
    __syncthreads();
    for (int e = tid; e < Ev; e += 1024) atomicAdd(&cnt[psm[e]], 1);
    for (int n = tid; n < Nn; n += 1024) atomicAdd(&lvl[(n >> 7) * 32 + hsm[n]], 1);
    __syncthreads();
    if (tid < 256) { int s = 0; for (int i = 0; i < 8; i++) s += cnt[tid * 8 + i]; part[tid] = s; }
    __syncthreads();
    if (tid == 0) {
        int run = 0;
        for (int i = 0; i < 256; i++) { int v = part[i]; part[i] = run; run += v; }
    }
    if (tid < 16) {                            // per-tree level prefix + maxlev
        int run = 0, mx = 1;
        for (int l = 0; l < 32; l++) {
            loff[tid * 32 + l] = tid * 128 + run;
            if (lvl[tid * 32 + l] > 0) mx = l;
            run += lvl[tid * 32 + l];
        }
        g_tmax[tid] = mx;
    }
    __syncthreads();
    for (int i = tid; i < 512; i += 1024) g_tl_off[i] = loff[i];
    if (tid < 256) {
        int run = part[tid];
        for (int i = 0; i < 8; i++) { int idx = tid * 8 + i; g_coff[idx] = run; run += cnt[idx]; }
        if (tid == 255) g_coff[Nn] = run;
    }
    __syncthreads();
    // deterministic CSR scatter: rank = #earlier same-parent edges (same batch)
    for (int e = tid; e < Ev; e += 1024) {
        int p = psm[e];
        int bstart = (e / (Sv - 1)) * (Sv - 1);
        int rank = 0;
        for (int e2 = bstart; e2 < e; e2++) rank += (psm[e2] == p);
        g_children[g_coff[p] + rank] = child_idx[e];
    }
    // per-tree level bucket fill (intra-level order numerically irrelevant)
    for (int n = tid; n < Nn; n += 1024) {
        int key = (n >> 7) * 32 + hsm[n];
        int r = atomicAdd(&lfill[key], 1);
        g_tl_nodes[loff[key] + r] = n;
    }
}

// ---------------- persistent kernel: crossbar-lean batched matvecs --------
__global__ void __launch_bounds__(NTHR, 1)
main_kernel(const int* __restrict__ xs, const int* __restrict__ rels,
            const float* __restrict__ emb_W, const float* __restrict__ rel_W,
            const float* __restrict__ W_ix, const float* __restrict__ b_ix,
            const float* __restrict__ W_ih, const float* __restrict__ b_ih,
            const float* __restrict__ W_fx, const float* __restrict__ b_fx,
            const float* __restrict__ W_fh, const float* __restrict__ b_fh,
            const float* __restrict__ W_ox, const float* __restrict__ W_oh,
            const float* __restrict__ W_ux, const float* __restrict__ W_uh,
            const float* __restrict__ W_out, const float* __restrict__ b_out,
            float* __restrict__ out) {
    extern __shared__ float sm[];
    float* Wi4 = sm;                  // col-slice layout [(k>>2)*128 + col*4 + (k&3)]
    float* Wo4 = sm + 8192;
    float* Wu4 = sm + 16384;
    float* Wf4 = sm + 24576;
    float* scratch = sm + 32768;      // 16384 floats = 16 warps x 1024
    int*   meta = (int*)(sm + 49152); // 512 ints
    int* sm_tloff = meta;             // 33
    int* sm_tln   = meta + 33;        // 128 node ids (global)
    int* sm_coff  = meta + 161;       // 129, rebased
    int* sm_child = meta + 290;       // <=127 child node ids (global)

    const int tid  = threadIdx.x;
    const int lane = tid & 31;
    const int warp = tid >> 5;
    const int blk  = blockIdx.x;
    const int b    = blk >> 3;        // tree id
    const int g    = blk & 7;         // column group
    const int J    = g * 32 + lane;
    float* xw = scratch + warp * 1024; // 4 nodes x 256 staging

    // ---- phase 0: weights (input-side) + tree metadata -> smem -----------
    {
        const int jb2 = g * 32;
        for (int it = 0; it < 16; it++) {
            int k = it * 16 + (tid >> 5);
            int col = tid & 31;
            int didx = (k >> 2) * 128 + col * 4 + (k & 3);
            int sidx = k * Hv + jb2 + col;
            Wi4[didx] = W_ix[sidx];
            Wo4[didx] = W_ox[sidx];
            Wu4[didx] = W_ux[sidx];
            Wf4[didx] = W_fx[sidx];
        }
        if (tid < 32) sm_tloff[tid] = g_tl_off[b * 32 + tid] - b * 128;
        if (tid >= 32 && tid < 160) sm_tln[tid - 32] = g_tl_nodes[b * 128 + (tid - 32)];
        int cbase = g_coff[b * 128];
        int cend  = g_coff[b * 128 + 128];
        if (tid >= 160 && tid < 289) sm_coff[tid - 160] = g_coff[b * 128 + (tid - 160)] - cbase;
        for (int i = tid; i < cend - cbase; i += NTHR) sm_child[i] = g_children[cbase + i];
    }
    const float bi = b_ix[J] + b_ih[J];
    const float bf = b_fx[J] + b_fh[J];
    __syncthreads();

    // ---- P1: 4 projections, columns J, 4 nodes per warp-iteration --------
    {
        for (int t = 0; t < 2; t++) {
            int nb = b * Sv + (warp + t * 16) * 4;   // 4 contiguous nodes
            __syncwarp();
            #pragma unroll
            for (int mm = 0; mm < 4; mm++) {
                int n = nb + mm;
                const float4* er = (const float4*)(emb_W + (size_t)xs[n] * DEv);
                const float4* rr = (const float4*)(rel_W + (size_t)rels[n] * DRv);
                float4 a = er[lane];
                float4 bb = (lane < 16) ? er[lane + 32] : rr[lane - 16];
                float4* dm = (float4*)(xw + mm * 256);
                dm[lane] = a; dm[lane + 32] = bb;
            }
            __syncwarp();
            unsigned long long acc[16];
            #pragma unroll
            for (int q = 0; q < 16; q++) acc[q] = 0ull;
            #pragma unroll 4
            for (int k4 = 0; k4 < 64; k4++) {
                ulonglong2 wi = *(const ulonglong2*)&Wi4[k4 * 128 + lane * 4];
                ulonglong2 wf = *(const ulonglong2*)&Wf4[k4 * 128 + lane * 4];
                ulonglong2 wo = *(const ulonglong2*)&Wo4[k4 * 128 + lane * 4];
                ulonglong2 wu = *(const ulonglong2*)&Wu4[k4 * 128 + lane * 4];
                #pragma unroll
                for (int mm = 0; mm < 4; mm++) {
                    ulonglong2 xv = *(const ulonglong2*)&xw[mm * 256 + k4 * 4];
                    FFMA2(acc[mm * 4 + 0], xv.x, wi.x); FFMA2(acc[mm * 4 + 0], xv.y, wi.y);
                    FFMA2(acc[mm * 4 + 1], xv.x, wf.x); FFMA2(acc[mm * 4 + 1], xv.y, wf.y);
                    FFMA2(acc[mm * 4 + 2], xv.x, wo.x); FFMA2(acc[mm * 4 + 2], xv.y, wo.y);
                    FFMA2(acc[mm * 4 + 3], xv.x, wu.x); FFMA2(acc[mm * 4 + 3], xv.y, wu.y);
                }
            }
            #pragma unroll
            for (int mm = 0; mm < 4; mm++) {
                size_t nx = (size_t)(nb + mm) * Hv + J;
                g_proj[0][nx] = pairsum(acc[mm * 4 + 0]) + bi;
                g_proj[1][nx] = pairsum(acc[mm * 4 + 1]) + bf;
                g_proj[2][nx] = pairsum(acc[mm * 4 + 2]);
                g_proj[3][nx] = pairsum(acc[mm * 4 + 3]);
            }
        }
    }
    __syncthreads();

    // ---- reload RECURRENT weight col-slices ------------------------------
    {
        const int jb2 = g * 32;
        for (int it = 0; it < 16; it++) {
            int k = it * 16 + (tid >> 5);
            int col = tid & 31;
            int didx = (k >> 2) * 128 + col * 4 + (k & 3);
            int sidx = k * Hv + jb2 + col;
            Wi4[didx] = W_ih[sidx];
            Wo4[didx] = W_oh[sidx];
            Wu4[didx] = W_uh[sidx];
            Wf4[didx] = W_fh[sidx];
        }
    }
    __syncthreads();

    // ---- level 0 (leaves): elementwise -----------------------------------
    {
        int lb = sm_tloff[0], le = sm_tloff[1];
        for (int idx = lb + warp; idx < le; idx += 16) {
            int n = sm_tln[idx];
            size_t nx = (size_t)n * Hv + J;
            float iv = sigf(g_proj[0][nx]);
            float ov = sigf(g_proj[2][nx]);
            float uv = __tanhf(g_proj[3][nx]);
            float cv = iv * uv;
            g_c[nx] = cv;
            g_h[nx] = ov * __tanhf(cv);
        }
    }
    __syncthreads();
    if (tid == 0) st_rel(&g_lflag[(b * NLEVF + 0) * 8 + g], 1u);

    // ---- bottom-up levels: adaptive batch, one flag per level ------------
    {
        const int tmax = g_tmax[b];
        for (int lev = 1; lev <= tmax; lev++) {
            // one-hop wait: all 8 CTAs of my tree published level lev-1
            if (warp == 0) {
                unsigned* fp = &g_lflag[(b * NLEVF + lev - 1) * 8 + (lane & 7)];
                for (;;) {
                    unsigned d = (lane < 8) ? ld_acq(fp) : 1u;
                    if (__all_sync(0xFFFFFFFFu, d != 0u)) break;
                }
            }
            __syncthreads();

            // (a) fh-phase: fh = W_fh . h for nodes of height lev-1
            {
                int pb = sm_tloff[lev - 1], pe = sm_tloff[lev];
                int pc = pe - pb;
                int cw = (pc + 15) >> 4; if (cw > 4) cw = 4; if (cw < 1) cw = 1;
                for (int i0 = pb + warp * cw; i0 < pe; i0 += 16 * cw) {
                    int mc = pe - i0; if (mc > cw) mc = cw;
                    if (mc == 1) {
                        int n = sm_tln[i0];
                        const float4* hsrc = (const float4*)(g_h + (size_t)n * Hv);
                        __syncwarp();
                        ((float4*)xw)[lane] = hsrc[lane];
                        ((float4*)xw)[lane + 32] = hsrc[lane + 32];
                        __syncwarp();
                        unsigned long long aX = 0, aY = 0;
                        #pragma unroll 8
                        for (int k4 = 0; k4 < 64; k4++) {
                            ulonglong2 wf = *(const ulonglong2*)&Wf4[k4 * 128 + lane * 4];
                            ulonglong2 xv = *(const ulonglong2*)&xw[k4 * 4];
                            FFMA2(aX, xv.x, wf.x); FFMA2(aY, xv.y, wf.y);
                        }
                        g_fh[(size_t)n * Hv + J] = pairsum(aX) + pairsum(aY);
                    } else {
                        int nid[4];
                        __syncwarp();
                        #pragma unroll
                        for (int mm = 0; mm < 4; mm++) {
                            if (mm < mc) {
                                int n = sm_tln[i0 + mm];
                                nid[mm] = n;
                                const float4* hsrc = (const float4*)(g_h + (size_t)n * Hv);
                                float4* dm = (float4*)(xw + mm * 256);
                                dm[lane] = hsrc[lane];
                                dm[lane + 32] = hsrc[lane + 32];
                            } else nid[mm] = -1;
                        }
                        __syncwarp();
                        unsigned long long af[4] = {0, 0, 0, 0};
                        #pragma unroll 4
                        for (int k4 = 0; k4 < 64; k4++) {
                            ulonglong2 wf = *(const ulonglong2*)&Wf4[k4 * 128 + lane * 4];
                            #pragma unroll
                            for (int mm = 0; mm < 4; mm++) {
                                ulonglong2 xv = *(const ulonglong2*)&xw[mm * 256 + k4 * 4];
                                FFMA2(af[mm], xv.x, wf.x); FFMA2(af[mm], xv.y, wf.y);
                            }
                        }
                        #pragma unroll
                        for (int mm = 0; mm < 4; mm++)
                            if (nid[mm] >= 0)
                                g_fh[(size_t)nid[mm] * Hv + J] = pairsum(af[mm]);
                    }
                }
            }
            __syncthreads();

            // (b) gate-phase: nodes of height lev, adaptive batch
            {
                int base = sm_tloff[lev], lend = sm_tloff[lev + 1];
                int cnt = lend - base;
                int cw = (cnt + 15) >> 4; if (cw > 4) cw = 4; if (cw < 1) cw = 1;
                for (int i0 = base + warp * cw; i0 < lend; i0 += 16 * cw) {
                    int mc = lend - i0; if (mc > cw) mc = cw;
                    if (mc == 1) {
                        int n = sm_tln[i0];
                        int nloc = n - b * Sv;
                        float fx = g_proj[1][(size_t)n * Hv + J];
                        int cs = sm_coff[nloc], ce = sm_coff[nloc + 1];
                        float4 s0 = make_float4(0, 0, 0, 0), s1 = make_float4(0, 0, 0, 0);
                        float fc = 0.0f;
                        for (int ci = cs; ci < ce; ci++) {
                            int ch = sm_child[ci];
                            const float4* hsrc = (const float4*)(g_h + (size_t)ch * Hv);
                            float4 v0 = hsrc[lane], v1 = hsrc[lane + 32];
                            s0.x += v0.x; s0.y += v0.y; s0.z += v0.z; s0.w += v0.w;
                            s1.x += v1.x; s1.y += v1.y; s1.z += v1.z; s1.w += v1.w;
                            fc += sigf(g_fh[(size_t)ch * Hv + J] + fx)
                                  * g_c[(size_t)ch * Hv + J];
                        }
                        __syncwarp();
                        ((float4*)xw)[lane] = s0; ((float4*)xw)[lane + 32] = s1;
                        __syncwarp();
                        unsigned long long ai = 0, aj = 0, ao = 0, ap = 0, au = 0, av = 0;
                        #pragma unroll 4
                        for (int k4 = 0; k4 < 64; k4++) {
                            ulonglong2 xv = *(const ulonglong2*)&xw[k4 * 4];
                            ulonglong2 wi = *(const ulonglong2*)&Wi4[k4 * 128 + lane * 4];
                            ulonglong2 wo = *(const ulonglong2*)&Wo4[k4 * 128 + lane * 4];
                            ulonglong2 wu = *(const ulonglong2*)&Wu4[k4 * 128 + lane * 4];
                            FFMA2(ai, xv.x, wi.x); FFMA2(aj, xv.y, wi.y);
                            FFMA2(ao, xv.x, wo.x); FFMA2(ap, xv.y, wo.y);
                            FFMA2(au, xv.x, wu.x); FFMA2(av, xv.y, wu.y);
                        }
                        size_t nx = (size_t)n * Hv + J;
                        float iv = sigf(g_proj[0][nx] + pairsum(ai) + pairsum(aj));
                        float ov = sigf(g_proj[2][nx] + pairsum(ao) + pairsum(ap));
                        float uv = __tanhf(g_proj[3][nx] + pairsum(au) + pairsum(av));
                        float cn = iv * uv + fc;
                        g_c[nx] = cn;
                        g_h[nx] = ov * __tanhf(cn);
                    } else {
                        int nid[4]; float fcv[4];
                        __syncwarp();
                        #pragma unroll
                        for (int mm = 0; mm < 4; mm++) {
                            fcv[mm] = 0.0f;
                            if (mm < mc) {
                                int n = sm_tln[i0 + mm];
                                nid[mm] = n;
                                int nloc = n - b * Sv;
                                float fx = g_proj[1][(size_t)n * Hv + J];
                                int cs = sm_coff[nloc], ce = sm_coff[nloc + 1];
                                float4 s0 = make_float4(0, 0, 0, 0);
                                float4 s1 = make_float4(0, 0, 0, 0);
                                float fc = 0.0f;
                                for (int ci = cs; ci < ce; ci++) {
                                    int ch = sm_child[ci];
                                    const float4* hsrc = (const float4*)(g_h + (size_t)ch * Hv);
                                    float4 v0 = hsrc[lane], v1 = hsrc[lane + 32];
                                    s0.x += v0.x; s0.y += v0.y; s0.z += v0.z; s0.w += v0.w;
                                    s1.x += v1.x; s1.y += v1.y; s1.z += v1.z; s1.w += v1.w;
                                    fc += sigf(g_fh[(size_t)ch * Hv + J] + fx)
                                          * g_c[(size_t)ch * Hv + J];
                                }
                                float4* dm = (float4*)(xw + mm * 256);
                                dm[lane] = s0; dm[lane + 32] = s1;
                                fcv[mm] = fc;
                            } else nid[mm] = -1;
                        }
                        __syncwarp();
                        unsigned long long ai[4] = {0, 0, 0, 0};
                        unsigned long long ao[4] = {0, 0, 0, 0};
                        unsigned long long au[4] = {0, 0, 0, 0};
                        #pragma unroll 2
                        for (int k4 = 0; k4 < 64; k4++) {
                            ulonglong2 wi = *(const ulonglong2*)&Wi4[k4 * 128 + lane * 4];
                            ulonglong2 wo = *(const ulonglong2*)&Wo4[k4 * 128 + lane * 4];
                            ulonglong2 wu = *(const ulonglong2*)&Wu4[k4 * 128 + lane * 4];
                            #pragma unroll
                            for (int mm = 0; mm < 4; mm++) {
                                ulonglong2 xv = *(const ulonglong2*)&xw[mm * 256 + k4 * 4];
                                FFMA2(ai[mm], xv.x, wi.x); FFMA2(ai[mm], xv.y, wi.y);
                                FFMA2(ao[mm], xv.x, wo.x); FFMA2(ao[mm], xv.y, wo.y);
                                FFMA2(au[mm], xv.x, wu.x); FFMA2(au[mm], xv.y, wu.y);
                            }
                        }
                        #pragma unroll
                        for (int mm = 0; mm < 4; mm++) {
                            if (nid[mm] < 0) continue;
                            size_t nx = (size_t)nid[mm] * Hv + J;
                            float iv = sigf(g_proj[0][nx] + pairsum(ai[mm]));
                            float ov = sigf(g_proj[2][nx] + pairsum(ao[mm]));
                            float uv = __tanhf(g_proj[3][nx] + pairsum(au[mm]));
                            float cn = iv * uv + fcv[mm];
                            g_c[nx] = cn;
                            g_h[nx] = ov * __tanhf(cn);
                        }
                    }
                }
            }
            __syncthreads();
            if (tid == 0) st_rel(&g_lflag[(b * NLEVF + lev) * 8 + g], 1u);
        }
    }

    // ---- pooling (column-local) + head -----------------------------------
    __syncthreads();
    {
        float m = -1e30f;
        for (int s2 = warp; s2 < Sv; s2 += 16)
            m = fmaxf(m, g_h[(size_t)(b * Sv + s2) * Hv + J]);
        scratch[warp * 32 + lane] = m;
        __syncthreads();
        if (tid < 32) {
            float mm = scratch[tid];
            #pragma unroll
            for (int r = 1; r < 16; r++) mm = fmaxf(mm, scratch[r * 32 + tid]);
            g_pooled[b * Hv + g * 32 + tid] = mm;
        }
        __syncthreads();
        if (tid == 0) red_add_rel(&g_pdone[b * 32], 1u);
    }
    if (g == 0) {
        if (tid == 0) { while (ld_acq(&g_pdone[b * 32]) < 8u) { } }
        __syncthreads();
        if (warp < Lv) {
            float acc = 0.0f;
            for (int k = lane; k < Hv; k += 32)
                acc += g_pooled[b * Hv + k] * W_out[k * Lv + warp];
            #pragma unroll
            for (int off = 16; off; off >>= 1)
                acc += __shfl_down_sync(0xFFFFFFFFu, acc, off);
            if (lane == 0) out[b * Lv + warp] = acc + b_out[warp];
        }
    }
}

// ---------------- launch --------------------------------------------------
extern "C" void kernel_launch(void* const* d_in, const int* in_sizes, int n_in,
                              void* d_out, int out_size) {
    const int s = (n_in >= 22) ? 1 : 0;   // robust to n_levels scalar presence
    const int* xs          = (const int*)d_in[0];
    const int* rels        = (const int*)d_in[1];
    const int* child_idx   = (const int*)d_in[2];
    const int* parent_idx  = (const int*)d_in[3];
    const int* node_height = (const int*)d_in[4];
    const float* emb_W = (const float*)d_in[5 + s];
    const float* rel_W = (const float*)d_in[6 + s];
    const float* W_ix  = (const float*)d_in[7 + s];
    const float* b_ix  = (const float*)d_in[8 + s];
    const float* W_ih  = (const float*)d_in[9 + s];
    const float* b_ih  = (const float*)d_in[10 + s];
    const float* W_fx  = (const float*)d_in[11 + s];
    const float* b_fx  = (const float*)d_in[12 + s];
    const float* W_fh  = (const float*)d_in[13 + s];
    const float* b_fh  = (const float*)d_in[14 + s];
    const float* W_ox  = (const float*)d_in[15 + s];
    const float* W_oh  = (const float*)d_in[16 + s];
    const float* W_ux  = (const float*)d_in[17 + s];
    const float* W_uh  = (const float*)d_in[18 + s];
    const float* W_out = (const float*)d_in[19 + s];
    const float* b_out = (const float*)d_in[20 + s];
    float* out = (float*)d_out;

    cudaFuncSetAttribute(main_kernel, cudaFuncAttributeMaxDynamicSharedMemorySize, SMEM_BYTES);

    setup_kernel<<<1, 1024>>>(child_idx, parent_idx, node_height);
    main_kernel<<<NCTA, NTHR, SMEM_BYTES>>>(xs, rels, emb_W, rel_W,
                                            W_ix, b_ix, W_ih, b_ih,
                                            W_fx, b_fx, W_fh, b_fh,
                                            W_ox, W_oh, W_ux, W_uh,
                                            W_out, b_out, out);
}